// round 14
// baseline (speedup 1.0000x reference)
#include <cuda_runtime.h>
#include <cuda_bf16.h>
#include <math.h>
#include <stdint.h>

#define HW 4096
#define NB 8
#define BSTR 136      // B smem row stride (halves)

// ---------------- scratch (device globals) ---------------------------------
__device__ float g_y[NB * 1024 * HW];                       // concat(cv1,cv2) fp32
__device__ __nv_bfloat16 g_x0h[NB * 512 * HW], g_x0l[NB * 512 * HW];     // split input x
__device__ __nv_bfloat16 g_xh1[NB * 1024 * HW], g_xl1[NB * 1024 * HW];   // cv1 input
__device__ __nv_bfloat16 g_xh2[NB * 1024 * HW], g_xl2[NB * 1024 * HW];   // cv2 input
__device__ __nv_bfloat16 g_bh [NB * 1024 * HW], g_bl [NB * 1024 * HW];   // c1 input (dw out)
__device__ __nv_bfloat16 g_gh [NB * 1024 * HW], g_gl [NB * 1024 * HW];   // cvend input (gated)
// fragment-packed weights (uint4 per lane per 16x16 tile), hi/lo splits
__device__ uint4 g_wfs_h[256 * 512 / 8],   g_wfs_l[256 * 512 / 8];    // sta
__device__ uint4 g_wf1_h[512 * 1024 / 8],  g_wf1_l[512 * 1024 / 8];   // cv1
__device__ uint4 g_wf2_h[512 * 1024 / 8],  g_wf2_l[512 * 1024 / 8];   // cv2
__device__ uint4 g_wfe_h[512 * 1024 / 8],  g_wfe_l[512 * 1024 / 8];   // cvend
__device__ uint4 g_wfc_h[1024 * 1024 / 8], g_wfc_l[1024 * 1024 / 8];  // c1

// ---------------- helpers ---------------------------------------------------
__device__ __forceinline__ void ldsm4t(unsigned* r, const __nv_bfloat16* p) {
    unsigned a = (unsigned)__cvta_generic_to_shared(p);
    asm volatile("ldmatrix.sync.aligned.m8n8.x4.trans.shared.b16 {%0,%1,%2,%3},[%4];"
        : "=r"(r[0]), "=r"(r[1]), "=r"(r[2]), "=r"(r[3]) : "r"(a));
}
__device__ __forceinline__ void mma16816(float* d, const unsigned* a, const unsigned* b) {
    asm volatile("mma.sync.aligned.m16n8k16.row.col.f32.bf16.bf16.f32 "
        "{%0,%1,%2,%3},{%4,%5,%6,%7},{%8,%9},{%0,%1,%2,%3};"
        : "+f"(d[0]), "+f"(d[1]), "+f"(d[2]), "+f"(d[3])
        : "r"(a[0]), "r"(a[1]), "r"(a[2]), "r"(a[3]), "r"(b[0]), "r"(b[1]));
}
__device__ __forceinline__ void pack2(float a, float b, uint32_t& h, uint32_t& l) {
    __nv_bfloat16 ha = __float2bfloat16(a), hb = __float2bfloat16(b);
    __nv_bfloat162 hp(ha, hb);
    __nv_bfloat162 lp(__float2bfloat16(a - __bfloat162float(ha)),
                      __float2bfloat16(b - __bfloat162float(hb)));
    h = *(uint32_t*)&hp; l = *(uint32_t*)&lp;
}
__device__ __forceinline__ float silu(float v) { return v / (1.f + __expf(-v)); }

// ---------------- fp32 -> bf16 hi/lo split (activations) -------------------
__global__ void split2(const float* __restrict__ in, __nv_bfloat16* __restrict__ hi,
                       __nv_bfloat16* __restrict__ lo, int n4)
{
    int i = blockIdx.x * blockDim.x + threadIdx.x;
    if (i >= n4) return;
    float4 v = ((const float4*)in)[i];
    uint32_t h0, l0, h1, l1;
    pack2(v.x, v.y, h0, l0);
    pack2(v.z, v.w, h1, l1);
    ((uint32_t*)hi)[i * 2] = h0;     ((uint32_t*)hi)[i * 2 + 1] = h1;
    ((uint32_t*)lo)[i * 2] = l0;     ((uint32_t*)lo)[i * 2 + 1] = l1;
}

// ---------------- weight pack: fp32 [M,K] -> mma A-fragment layout ---------
// tile (mt,kt) covers rows mt*16..+15, cols kt*16..+15; lane l holds
// a0={W[r][c],W[r][c+1]} a1={r+8} a2={c+8} a3={r+8,c+8}, r=mt*16+(l>>2), c=kt*16+(l&3)*2
__global__ void packW(const float* __restrict__ W, uint4* __restrict__ fh,
                      uint4* __restrict__ fl, int M, int K)
{
    int idx = blockIdx.x * blockDim.x + threadIdx.x;
    int total = (M / 16) * (K / 16) * 32;
    if (idx >= total) return;
    int lane = idx & 31, tile = idx >> 5;
    int ktiles = K / 16;
    int mt = tile / ktiles, kt = tile % ktiles;
    int row = mt * 16 + (lane >> 2);
    int col = kt * 16 + (lane & 3) * 2;
    const float* p0 = W + (size_t)row * K + col;
    const float* p1 = W + (size_t)(row + 8) * K + col;
    uint32_t h0, l0, h1, l1, h2, l2, h3, l3;
    pack2(p0[0], p0[1], h0, l0);
    pack2(p1[0], p1[1], h1, l1);
    pack2(p0[8], p0[9], h2, l2);
    pack2(p1[8], p1[9], h3, l3);
    fh[idx] = make_uint4(h0, h1, h2, h3);
    fl[idx] = make_uint4(l0, l1, l2, l3);
}

// ---------------- GEMM: A frags from gmem (L2), B via smem+ldsm ------------
// 256 threads, 2x4 warps, warp tile 64x32, block tile 128x128x32
// EPI: 0 = fp32 store; 1 = split dup store (sta); 2 = gate with Ygate, split (c1)
template<int ACT, int EPI>
__global__ void __launch_bounds__(256, 1)
gemm_fragA(const uint4* __restrict__ WfH, const uint4* __restrict__ WfL,
           const __nv_bfloat16* __restrict__ Bhi, const __nv_bfloat16* __restrict__ Blo,
           const float* __restrict__ bias, float* __restrict__ Yf,
           const float* __restrict__ Ygate,
           __nv_bfloat16* __restrict__ o1h, __nv_bfloat16* __restrict__ o1l,
           __nv_bfloat16* __restrict__ o2h, __nv_bfloat16* __restrict__ o2l,
           int K, int outCtot, int coff)
{
    extern __shared__ __align__(16) char smraw[];
    __nv_bfloat16* sB = (__nv_bfloat16*)smraw;       // [2 par][2 split][32][BSTR]

    const int tid = threadIdx.x;
    const int lane = tid & 31, warp = tid >> 5;
    const int wm = warp >> 2, wn = warp & 3;
    const int m0 = blockIdx.x * 128;
    const int hw0 = blockIdx.y * 128;
    const int bz = blockIdx.z;
    const size_t xoff = (size_t)bz * K * HW;
    const int iters = K / 32;
    const int ktiles = K / 16;
    const int mbase = (m0 >> 4) + wm * 4;

    // B loader coords: 512 uint4s/tile-split, 2 per thread
    int bKr[2], bNg[2];
#pragma unroll
    for (int e = 0; e < 2; e++) {
        int i = tid + e * 256;
        bKr[e] = i >> 4;  bNg[e] = (i & 15) * 8;
    }
    uint4 rbh[2], rbl[2];
    auto loadRegsB = [&](int it) {
        int k0 = it * 32;
#pragma unroll
        for (int e = 0; e < 2; e++) {
            size_t gb = xoff + (size_t)(k0 + bKr[e]) * HW + hw0 + bNg[e];
            rbh[e] = *(const uint4*)(Bhi + gb);
            rbl[e] = *(const uint4*)(Blo + gb);
        }
    };
    auto stsRegsB = [&](int p) {
#pragma unroll
        for (int e = 0; e < 2; e++) {
            *(uint4*)(sB + ((p * 2 + 0) * 32 + bKr[e]) * BSTR + bNg[e]) = rbh[e];
            *(uint4*)(sB + ((p * 2 + 1) * 32 + bKr[e]) * BSTR + bNg[e]) = rbl[e];
        }
    };

    // A fragment double buffer (per ks-step)
    uint4 afh[2][4], afl[2][4];
    auto loadA = [&](int buf, int kt) {
#pragma unroll
        for (int mt = 0; mt < 4; mt++) {
            size_t fi = ((size_t)(mbase + mt) * ktiles + kt) * 32 + lane;
            afh[buf][mt] = WfH[fi];
            afl[buf][mt] = WfL[fi];
        }
    };

    float acc[4][4][4];
#pragma unroll
    for (int i = 0; i < 4; i++)
#pragma unroll
        for (int j = 0; j < 4; j++)
#pragma unroll
            for (int q = 0; q < 4; q++) acc[i][j][q] = 0.f;

    const int bkrow = (lane & 7) + ((lane & 8) ? 8 : 0);
    const int bcol8 = (lane & 16) ? 8 : 0;

    loadRegsB(0);
    stsRegsB(0);
    if (iters > 1) loadRegsB(1);
    loadA(0, 0);
    __syncthreads();

    int p = 0;
    for (int it = 0; it < iters; it++) {
        if (it + 1 < iters) stsRegsB(p ^ 1);
        if (it + 2 < iters) loadRegsB(it + 2);

#pragma unroll
        for (int ks = 0; ks < 2; ks++) {
            const int kt = it * 2 + ks;
            const int buf = kt & 1;
            if (kt + 1 < 2 * iters) loadA(buf ^ 1, kt + 1);

            unsigned bh[4][2], bl[4][2];
            const int krow = ks * 16 + bkrow;
#pragma unroll
            for (int q = 0; q < 2; q++) {
                int j0 = wn * 32 + q * 16 + bcol8;
                unsigned r[4];
                ldsm4t(r, sB + ((p * 2 + 0) * 32 + krow) * BSTR + j0);
                bh[q * 2][0] = r[0]; bh[q * 2][1] = r[1];
                bh[q * 2 + 1][0] = r[2]; bh[q * 2 + 1][1] = r[3];
                ldsm4t(r, sB + ((p * 2 + 1) * 32 + krow) * BSTR + j0);
                bl[q * 2][0] = r[0]; bl[q * 2][1] = r[1];
                bl[q * 2 + 1][0] = r[2]; bl[q * 2 + 1][1] = r[3];
            }
#pragma unroll
            for (int mt = 0; mt < 4; mt++) {
                const unsigned* ah = (const unsigned*)&afh[buf][mt];
                const unsigned* al = (const unsigned*)&afl[buf][mt];
#pragma unroll
                for (int nt = 0; nt < 4; nt++) {
                    mma16816(acc[mt][nt], ah, bh[nt]);
                    mma16816(acc[mt][nt], ah, bl[nt]);
                    mma16816(acc[mt][nt], al, bh[nt]);
                }
            }
        }
        __syncthreads();
        p ^= 1;
    }

    // ---------------- epilogue ----------------
    const int r0 = lane >> 2, c0 = (lane & 3) * 2;
#pragma unroll
    for (int mt = 0; mt < 4; mt++) {
        int mA = m0 + wm * 64 + mt * 16 + r0;
        int mB = mA + 8;
        float bvA = bias[mA], bvB = bias[mB];
#pragma unroll
        for (int nt = 0; nt < 4; nt++) {
            int n = hw0 + wn * 32 + nt * 8 + c0;
            float v0 = acc[mt][nt][0] + bvA;
            float v1 = acc[mt][nt][1] + bvA;
            float v2 = acc[mt][nt][2] + bvB;
            float v3 = acc[mt][nt][3] + bvB;
            if (ACT) { v0 = silu(v0); v1 = silu(v1); v2 = silu(v2); v3 = silu(v3); }
            size_t oA = (size_t)bz * outCtot * HW + (size_t)(coff + mA) * HW + n;
            size_t oB = (size_t)bz * outCtot * HW + (size_t)(coff + mB) * HW + n;
            if (EPI == 0) {
                *(float2*)(Yf + oA) = make_float2(v0, v1);
                *(float2*)(Yf + oB) = make_float2(v2, v3);
            } else if (EPI == 1) {
                uint32_t h, l;
                pack2(v0, v1, h, l);
                *(uint32_t*)(o1h + oA) = h; *(uint32_t*)(o1l + oA) = l;
                *(uint32_t*)(o2h + oA) = h; *(uint32_t*)(o2l + oA) = l;
                pack2(v2, v3, h, l);
                *(uint32_t*)(o1h + oB) = h; *(uint32_t*)(o1l + oB) = l;
                *(uint32_t*)(o2h + oB) = h; *(uint32_t*)(o2l + oB) = l;
            } else {
                float2 yA = *(const float2*)(Ygate + oA);
                float2 yB = *(const float2*)(Ygate + oB);
                uint32_t h, l;
                pack2(v0 * yA.x, v1 * yA.y, h, l);
                *(uint32_t*)(o1h + oA) = h; *(uint32_t*)(o1l + oA) = l;
                pack2(v2 * yB.x, v3 * yB.y, h, l);
                *(uint32_t*)(o1h + oB) = h; *(uint32_t*)(o1l + oB) = l;
            }
        }
    }
}
#define GEMM_SMEM (2 * 2 * 32 * BSTR * 2)   // 34816 B (B tiles only)

// ---------------- fused dual-branch SPPF pooling (split I/O) ---------------
__global__ void __launch_bounds__(256)
pool_both(const __nv_bfloat16* __restrict__ xh, const __nv_bfloat16* __restrict__ xl,
          __nv_bfloat16* __restrict__ o1h, __nv_bfloat16* __restrict__ o1l,
          __nv_bfloat16* __restrict__ o2h, __nv_bfloat16* __restrict__ o2l)
{
    extern __shared__ float sp[];
    float* sx = sp;
    float* si = sp + 4096;
    float* pe = sp + 8192;
    float* t1 = sp + 12288;
    float* t2 = sp + 16384;
    const int ch = blockIdx.x, b = blockIdx.y;
    const int tid = threadIdx.x;
    const size_t src = ((size_t)b * 1024 + ch) * HW;

    for (int i = tid; i < 4096; i += 256) {
        float v = __bfloat162float(xh[src + i]) + __bfloat162float(xl[src + i]);
        sx[i] = v; si[i] = v;
    }
    __syncthreads();

    for (int s = 0; s < 3; s++) {
        for (int i = tid; i < 4096; i += 256) {
            int c = i & 63;
            const float* row = &si[i - c];
            float mx = -INFINITY, sm = 0.f;
#pragma unroll
            for (int d = -2; d <= 2; d++) {
                int cc = c + d;
                if (cc >= 0 && cc < 64) { float v = row[cc]; mx = fmaxf(mx, v); sm += v; }
            }
            t1[i] = mx; t2[i] = sm;
        }
        __syncthreads();
        size_t dst = ((size_t)b * 1024 + (s + 1) * 256 + ch) * HW;
        for (int i = tid; i < 4096; i += 256) {
            int c = i & 63, r = i >> 6;
            float mx = -INFINITY, sm = 0.f;
#pragma unroll
            for (int d = -2; d <= 2; d++) {
                int rr = r + d;
                if (rr >= 0 && rr < 64) { mx = fmaxf(mx, t1[rr * 64 + c]); sm += t2[rr * 64 + c]; }
            }
            float v = 0.9f * mx + 0.004f * sm;
            si[i] = v;
            __nv_bfloat16 h = __float2bfloat16(v);
            o1h[dst + i] = h;
            o1l[dst + i] = __float2bfloat16(v - __bfloat162float(h));
        }
        __syncthreads();
    }

    for (int i = tid; i < 4096; i += 256) si[i] = sx[i];
    __syncthreads();

    for (int s = 0; s < 3; s++) {
        for (int i = tid; i < 4096; i += 256) pe[i] = __expf(si[i]);
        __syncthreads();
        for (int i = tid; i < 4096; i += 256) {
            int c = i & 63;
            const float* erow = &pe[i - c];
            const float* vrow = &si[i - c];
            float se = 0.f, sex = 0.f;
#pragma unroll
            for (int d = -2; d <= 2; d++) {
                int cc = c + d;
                if (cc >= 0 && cc < 64) {
                    float e = erow[cc];
                    se += e; sex = fmaf(e, vrow[cc], sex);
                }
            }
            t1[i] = se; t2[i] = sex;
        }
        __syncthreads();
        size_t dst = ((size_t)b * 1024 + (s + 1) * 256 + ch) * HW;
        for (int i = tid; i < 4096; i += 256) {
            int c = i & 63, r = i >> 6;
            float den = 0.f, num = 0.f;
#pragma unroll
            for (int d = -2; d <= 2; d++) {
                int rr = r + d;
                if (rr >= 0 && rr < 64) { den += t1[rr * 64 + c]; num += t2[rr * 64 + c]; }
            }
            float v = num / (den + 1e-6f);
            si[i] = v;
            __nv_bfloat16 h = __float2bfloat16(v);
            o2h[dst + i] = h;
            o2l[dst + i] = __float2bfloat16(v - __bfloat162float(h));
        }
        __syncthreads();
    }
}
#define POOL_SMEM (5 * 4096 * 4)

// ---------------- fused LSKA depthwise chain (fp32 in, split out) ----------
__global__ void __launch_bounds__(256)
dw_fused(const float* __restrict__ y,
         const float* __restrict__ w1, const float* __restrict__ b1,
         const float* __restrict__ w2, const float* __restrict__ b2,
         const float* __restrict__ w3, const float* __restrict__ b3,
         const float* __restrict__ w4, const float* __restrict__ b4,
         __nv_bfloat16* __restrict__ oh, __nv_bfloat16* __restrict__ ol)
{
    __shared__ float s0[4096], s1[4096];
    const int ch = blockIdx.x, b = blockIdx.y;
    const int tid = threadIdx.x;
    const size_t off = ((size_t)b * 1024 + ch) * HW;

    for (int i = tid; i < 4096; i += 256) s0[i] = y[off + i];
    __syncthreads();

    {
        float wa = w1[ch * 3], wb = w1[ch * 3 + 1], wc = w1[ch * 3 + 2], bb = b1[ch];
        for (int i = tid; i < 4096; i += 256) {
            int c = i & 63;
            const float* row = &s0[i - c];
            float acc = bb + wb * row[c];
            if (c >= 1)  acc = fmaf(wa, row[c - 1], acc);
            if (c <= 62) acc = fmaf(wc, row[c + 1], acc);
            s1[i] = acc;
        }
    }
    __syncthreads();
    {
        float wa = w2[ch * 3], wb = w2[ch * 3 + 1], wc = w2[ch * 3 + 2], bb = b2[ch];
        for (int i = tid; i < 4096; i += 256) {
            int r = i >> 6;
            float acc = bb + wb * s1[i];
            if (r >= 1)  acc = fmaf(wa, s1[i - 64], acc);
            if (r <= 62) acc = fmaf(wc, s1[i + 64], acc);
            s0[i] = acc;
        }
    }
    __syncthreads();
    {
        float wa = w3[ch * 3], wb = w3[ch * 3 + 1], wc = w3[ch * 3 + 2], bb = b3[ch];
        for (int i = tid; i < 4096; i += 256) {
            int c = i & 63;
            const float* row = &s0[i - c];
            float acc = bb + wb * row[c];
            if (c >= 2)  acc = fmaf(wa, row[c - 2], acc);
            if (c <= 61) acc = fmaf(wc, row[c + 2], acc);
            s1[i] = acc;
        }
    }
    __syncthreads();
    {
        float wa = w4[ch * 3], wb = w4[ch * 3 + 1], wc = w4[ch * 3 + 2], bb = b4[ch];
        for (int i = tid; i < 4096; i += 256) {
            int r = i >> 6;
            float acc = bb + wb * s1[i];
            if (r >= 2)  acc = fmaf(wa, s1[i - 128], acc);
            if (r <= 61) acc = fmaf(wc, s1[i + 128], acc);
            __nv_bfloat16 h = __float2bfloat16(acc);
            oh[off + i] = h;
            ol[off + i] = __float2bfloat16(acc - __bfloat162float(h));
        }
    }
}

// ---------------- launch ----------------------------------------------------
extern "C" void kernel_launch(void* const* d_in, const int* in_sizes, int n_in,
                              void* d_out, int out_size)
{
    const float* x       = (const float*)d_in[0];
    const float* w_sta   = (const float*)d_in[1];
    const float* b_sta   = (const float*)d_in[2];
    const float* w_cv1   = (const float*)d_in[3];
    const float* b_cv1   = (const float*)d_in[4];
    const float* w_cv2   = (const float*)d_in[5];
    const float* b_cv2   = (const float*)d_in[6];
    const float* w_cvend = (const float*)d_in[7];
    const float* b_cvend = (const float*)d_in[8];
    const float* w_dwh   = (const float*)d_in[9];
    const float* b_dwh   = (const float*)d_in[10];
    const float* w_dwv   = (const float*)d_in[11];
    const float* b_dwv   = (const float*)d_in[12];
    const float* w_ddwh  = (const float*)d_in[13];
    const float* b_ddwh  = (const float*)d_in[14];
    const float* w_ddwv  = (const float*)d_in[15];
    const float* b_ddwv  = (const float*)d_in[16];
    const float* w_c1    = (const float*)d_in[17];
    const float* b_c1    = (const float*)d_in[18];

    float *y;
    __nv_bfloat16 *x0h, *x0l, *xh1, *xl1, *xh2, *xl2, *bh, *bl, *gh, *gl;
    uint4 *wfs_h, *wfs_l, *wf1_h, *wf1_l, *wf2_h, *wf2_l, *wfe_h, *wfe_l, *wfc_h, *wfc_l;
    cudaGetSymbolAddress((void**)&y,   g_y);
    cudaGetSymbolAddress((void**)&x0h, g_x0h); cudaGetSymbolAddress((void**)&x0l, g_x0l);
    cudaGetSymbolAddress((void**)&xh1, g_xh1); cudaGetSymbolAddress((void**)&xl1, g_xl1);
    cudaGetSymbolAddress((void**)&xh2, g_xh2); cudaGetSymbolAddress((void**)&xl2, g_xl2);
    cudaGetSymbolAddress((void**)&bh,  g_bh);  cudaGetSymbolAddress((void**)&bl,  g_bl);
    cudaGetSymbolAddress((void**)&gh,  g_gh);  cudaGetSymbolAddress((void**)&gl,  g_gl);
    cudaGetSymbolAddress((void**)&wfs_h, g_wfs_h); cudaGetSymbolAddress((void**)&wfs_l, g_wfs_l);
    cudaGetSymbolAddress((void**)&wf1_h, g_wf1_h); cudaGetSymbolAddress((void**)&wf1_l, g_wf1_l);
    cudaGetSymbolAddress((void**)&wf2_h, g_wf2_h); cudaGetSymbolAddress((void**)&wf2_l, g_wf2_l);
    cudaGetSymbolAddress((void**)&wfe_h, g_wfe_h); cudaGetSymbolAddress((void**)&wfe_l, g_wfe_l);
    cudaGetSymbolAddress((void**)&wfc_h, g_wfc_h); cudaGetSymbolAddress((void**)&wfc_l, g_wfc_l);

    cudaFuncSetAttribute(gemm_fragA<1, 1>, cudaFuncAttributeMaxDynamicSharedMemorySize, GEMM_SMEM);
    cudaFuncSetAttribute(gemm_fragA<1, 0>, cudaFuncAttributeMaxDynamicSharedMemorySize, GEMM_SMEM);
    cudaFuncSetAttribute(gemm_fragA<0, 2>, cudaFuncAttributeMaxDynamicSharedMemorySize, GEMM_SMEM);
    cudaFuncSetAttribute(pool_both, cudaFuncAttributeMaxDynamicSharedMemorySize, POOL_SMEM);
    auto g4 = [](int n) { return (n / 4 + 255) / 256; };
    auto gp = [](int M, int K) { return (M * K / 8 + 255) / 256; };

    // 0) one-shot: split input activations, frag-pack all weights
    split2<<<g4(NB * 512 * HW), 256>>>(x, x0h, x0l, NB * 512 * HW / 4);
    packW<<<gp(256, 512), 256>>>(w_sta, wfs_h, wfs_l, 256, 512);
    packW<<<gp(512, 1024), 256>>>(w_cv1, wf1_h, wf1_l, 512, 1024);
    packW<<<gp(512, 1024), 256>>>(w_cv2, wf2_h, wf2_l, 512, 1024);
    packW<<<gp(512, 1024), 256>>>(w_cvend, wfe_h, wfe_l, 512, 1024);
    packW<<<gp(1024, 1024), 256>>>(w_c1, wfc_h, wfc_l, 1024, 1024);

    // 1) sta: 512->256 + SiLU, split-dup into (xh1,xl1) and (xh2,xl2) ch 0..255
    gemm_fragA<1, 1><<<dim3(2, 32, NB), 256, GEMM_SMEM>>>(
        wfs_h, wfs_l, x0h, x0l, b_sta, nullptr, nullptr, xh1, xl1, xh2, xl2, 512, 1024, 0);

    // 2) fused dual-branch pooling (split buffers, ch 256..1023)
    pool_both<<<dim3(256, NB), 256, POOL_SMEM>>>(xh1, xl1, xh1, xl1, xh2, xl2);

    // 3) cv1 / cv2: 1024->512 + SiLU -> fp32 concat y
    gemm_fragA<1, 0><<<dim3(4, 32, NB), 256, GEMM_SMEM>>>(
        wf1_h, wf1_l, xh1, xl1, b_cv1, y, nullptr, nullptr, nullptr, nullptr, nullptr, 1024, 1024, 0);
    gemm_fragA<1, 0><<<dim3(4, 32, NB), 256, GEMM_SMEM>>>(
        wf2_h, wf2_l, xh2, xl2, b_cv2, y, nullptr, nullptr, nullptr, nullptr, nullptr, 1024, 1024, 512);

    // 4) fused LSKA depthwise chain: y -> split (bh,bl)
    dw_fused<<<dim3(1024, NB), 256>>>(y, w_dwh, b_dwh, w_dwv, b_dwv,
                                      w_ddwh, b_ddwh, w_ddwv, b_ddwv, bh, bl);

    // 5) c1: 1024->1024, gate with y, split -> (gh,gl)
    gemm_fragA<0, 2><<<dim3(8, 32, NB), 256, GEMM_SMEM>>>(
        wfc_h, wfc_l, bh, bl, b_c1, nullptr, y, gh, gl, nullptr, nullptr, 1024, 1024, 0);

    // 6) cvend: 1024->512 + SiLU -> fp32 output
    gemm_fragA<1, 0><<<dim3(4, 32, NB), 256, GEMM_SMEM>>>(
        wfe_h, wfe_l, gh, gl, b_cvend, (float*)d_out, nullptr, nullptr, nullptr, nullptr, nullptr,
        1024, 512, 0);
}

// round 15
// speedup vs baseline: 1.1860x; 1.1860x over previous
#include <cuda_runtime.h>
#include <cuda_bf16.h>
#include <math.h>
#include <stdint.h>

#define HW 4096
#define NB 8
#define ASTR 40       // A smem row stride (halves): 32 + 8 pad
#define BSTR 72       // B smem row stride (halves): 64 + 8 pad

// ---------------- scratch (device globals) ---------------------------------
__device__ float g_y[NB * 1024 * HW];                       // concat(cv1,cv2) fp32
__device__ __nv_bfloat16 g_x0h[NB * 512 * HW], g_x0l[NB * 512 * HW];     // split input x
__device__ __nv_bfloat16 g_xh1[NB * 1024 * HW], g_xl1[NB * 1024 * HW];   // cv1 input
__device__ __nv_bfloat16 g_xh2[NB * 1024 * HW], g_xl2[NB * 1024 * HW];   // cv2 input
__device__ __nv_bfloat16 g_bh [NB * 1024 * HW], g_bl [NB * 1024 * HW];   // c1 input (dw out)
__device__ __nv_bfloat16 g_gh [NB * 1024 * HW], g_gl [NB * 1024 * HW];   // cvend input (gated)
__device__ __nv_bfloat16 g_wsh[256 * 512],   g_wsl[256 * 512];
__device__ __nv_bfloat16 g_w1h[512 * 1024],  g_w1l[512 * 1024];
__device__ __nv_bfloat16 g_w2h[512 * 1024],  g_w2l[512 * 1024];
__device__ __nv_bfloat16 g_weh[512 * 1024],  g_wel[512 * 1024];
__device__ __nv_bfloat16 g_wch[1024 * 1024], g_wcl[1024 * 1024];

// ---------------- helpers ---------------------------------------------------
__device__ __forceinline__ void ldsm4(unsigned* r, const __nv_bfloat16* p) {
    unsigned a = (unsigned)__cvta_generic_to_shared(p);
    asm volatile("ldmatrix.sync.aligned.m8n8.x4.shared.b16 {%0,%1,%2,%3},[%4];"
        : "=r"(r[0]), "=r"(r[1]), "=r"(r[2]), "=r"(r[3]) : "r"(a));
}
__device__ __forceinline__ void ldsm4t(unsigned* r, const __nv_bfloat16* p) {
    unsigned a = (unsigned)__cvta_generic_to_shared(p);
    asm volatile("ldmatrix.sync.aligned.m8n8.x4.trans.shared.b16 {%0,%1,%2,%3},[%4];"
        : "=r"(r[0]), "=r"(r[1]), "=r"(r[2]), "=r"(r[3]) : "r"(a));
}
__device__ __forceinline__ void mma16816(float* d, const unsigned* a, const unsigned* b) {
    asm volatile("mma.sync.aligned.m16n8k16.row.col.f32.bf16.bf16.f32 "
        "{%0,%1,%2,%3},{%4,%5,%6,%7},{%8,%9},{%0,%1,%2,%3};"
        : "+f"(d[0]), "+f"(d[1]), "+f"(d[2]), "+f"(d[3])
        : "r"(a[0]), "r"(a[1]), "r"(a[2]), "r"(a[3]), "r"(b[0]), "r"(b[1]));
}
__device__ __forceinline__ void pack2(float a, float b, uint32_t& h, uint32_t& l) {
    __nv_bfloat16 ha = __float2bfloat16(a), hb = __float2bfloat16(b);
    __nv_bfloat162 hp(ha, hb);
    __nv_bfloat162 lp(__float2bfloat16(a - __bfloat162float(ha)),
                      __float2bfloat16(b - __bfloat162float(hb)));
    h = *(uint32_t*)&hp; l = *(uint32_t*)&lp;
}
__device__ __forceinline__ float silu(float v) { return v / (1.f + __expf(-v)); }

// ---------------- fp32 -> bf16 hi/lo split ---------------------------------
__global__ void split2(const float* __restrict__ in, __nv_bfloat16* __restrict__ hi,
                       __nv_bfloat16* __restrict__ lo, int n4)
{
    int i = blockIdx.x * blockDim.x + threadIdx.x;
    if (i >= n4) return;
    float4 v = ((const float4*)in)[i];
    uint32_t h0, l0, h1, l1;
    pack2(v.x, v.y, h0, l0);
    pack2(v.z, v.w, h1, l1);
    ((uint32_t*)hi)[i * 2] = h0;     ((uint32_t*)hi)[i * 2 + 1] = h1;
    ((uint32_t*)lo)[i * 2] = l0;     ((uint32_t*)lo)[i * 2 + 1] = l1;
}

// ---------------- GEMM: 128x64x32 tile, 2 CTAs/SM --------------------------
// D[m][n] = act(sum_k W[m,k] * X[k,n] + bias[m]),  m=outC, n=hw
// 256 threads, warp grid 4x2, warp tile 32x32; smem 58KB, regs<=128 -> occ 2
// EPI: 0 = fp32 store; 1 = split dup store (sta); 2 = gate with Ygate, split (c1)
template<int ACT, int EPI>
__global__ void __launch_bounds__(256, 2)
gemm_pre(const __nv_bfloat16* __restrict__ Ahi, const __nv_bfloat16* __restrict__ Alo,
         const __nv_bfloat16* __restrict__ Bhi, const __nv_bfloat16* __restrict__ Blo,
         const float* __restrict__ bias, float* __restrict__ Yf,
         const float* __restrict__ Ygate,
         __nv_bfloat16* __restrict__ o1h, __nv_bfloat16* __restrict__ o1l,
         __nv_bfloat16* __restrict__ o2h, __nv_bfloat16* __restrict__ o2l,
         int K, int outCtot, int coff)
{
    extern __shared__ __align__(16) char smraw[];
    __nv_bfloat16* sA = (__nv_bfloat16*)smraw;                 // [2 par][2 spl][128][ASTR]
    __nv_bfloat16* sB = sA + 2 * 2 * 128 * ASTR;               // [2 par][2 spl][32][BSTR]

    const int tid = threadIdx.x;
    const int lane = tid & 31, warp = tid >> 5;
    const int wm = warp >> 1, wn = warp & 1;   // 4 x 2 warp grid
    const int m0 = blockIdx.x * 128;
    const int hw0 = blockIdx.y * 64;
    const int bz = blockIdx.z;
    const size_t xoff = (size_t)bz * K * HW;
    const int iters = K / 32;

    // A loader: 512 uint4/split -> 2 per thread; B: 256 uint4/split -> 1 per thread
    int aRow[2], aKg[2];
#pragma unroll
    for (int e = 0; e < 2; e++) {
        int i = tid + e * 256;
        aRow[e] = i >> 2;  aKg[e] = (i & 3) * 8;
    }
    const int bKr = tid >> 3, bNg = (tid & 7) * 8;

    uint4 rah[2], ral[2], rbh, rbl;
    auto loadRegs = [&](int it) {
        int k0 = it * 32;
#pragma unroll
        for (int e = 0; e < 2; e++) {
            size_t ga = (size_t)(m0 + aRow[e]) * K + k0 + aKg[e];
            rah[e] = *(const uint4*)(Ahi + ga);
            ral[e] = *(const uint4*)(Alo + ga);
        }
        size_t gb = xoff + (size_t)(k0 + bKr) * HW + hw0 + bNg;
        rbh = *(const uint4*)(Bhi + gb);
        rbl = *(const uint4*)(Blo + gb);
    };
    auto stsRegs = [&](int p) {
#pragma unroll
        for (int e = 0; e < 2; e++) {
            *(uint4*)(sA + ((p * 2 + 0) * 128 + aRow[e]) * ASTR + aKg[e]) = rah[e];
            *(uint4*)(sA + ((p * 2 + 1) * 128 + aRow[e]) * ASTR + aKg[e]) = ral[e];
        }
        *(uint4*)(sB + ((p * 2 + 0) * 32 + bKr) * BSTR + bNg) = rbh;
        *(uint4*)(sB + ((p * 2 + 1) * 32 + bKr) * BSTR + bNg) = rbl;
    };

    float acc[2][4][4];
#pragma unroll
    for (int i = 0; i < 2; i++)
#pragma unroll
        for (int j = 0; j < 4; j++)
#pragma unroll
            for (int q = 0; q < 4; q++) acc[i][j][q] = 0.f;

    const int arow = lane & 15;
    const int acol8 = (lane >> 4) << 3;
    const int bkrow = (lane & 7) + ((lane & 8) ? 8 : 0);
    const int bcol8 = (lane & 16) ? 8 : 0;

    loadRegs(0);
    stsRegs(0);
    if (iters > 1) loadRegs(1);
    __syncthreads();

    int p = 0;
    for (int it = 0; it < iters; it++) {
        if (it + 1 < iters) stsRegs(p ^ 1);
        if (it + 2 < iters) loadRegs(it + 2);

#pragma unroll
        for (int ks = 0; ks < 2; ks++) {
            unsigned ah[2][4], al[2][4], bh[4][2], bl[4][2];
            const int acol = ks * 16 + acol8;
#pragma unroll
            for (int mt = 0; mt < 2; mt++) {
                int m = wm * 32 + mt * 16 + arow;
                ldsm4(ah[mt], sA + ((p * 2 + 0) * 128 + m) * ASTR + acol);
                ldsm4(al[mt], sA + ((p * 2 + 1) * 128 + m) * ASTR + acol);
            }
            const int krow = ks * 16 + bkrow;
#pragma unroll
            for (int q = 0; q < 2; q++) {
                int j0 = wn * 32 + q * 16 + bcol8;
                unsigned r[4];
                ldsm4t(r, sB + ((p * 2 + 0) * 32 + krow) * BSTR + j0);
                bh[q * 2][0] = r[0]; bh[q * 2][1] = r[1];
                bh[q * 2 + 1][0] = r[2]; bh[q * 2 + 1][1] = r[3];
                ldsm4t(r, sB + ((p * 2 + 1) * 32 + krow) * BSTR + j0);
                bl[q * 2][0] = r[0]; bl[q * 2][1] = r[1];
                bl[q * 2 + 1][0] = r[2]; bl[q * 2 + 1][1] = r[3];
            }
#pragma unroll
            for (int mt = 0; mt < 2; mt++)
#pragma unroll
                for (int nt = 0; nt < 4; nt++) {
                    mma16816(acc[mt][nt], ah[mt], bh[nt]);
                    mma16816(acc[mt][nt], ah[mt], bl[nt]);
                    mma16816(acc[mt][nt], al[mt], bh[nt]);
                }
        }
        __syncthreads();
        p ^= 1;
    }

    // ---------------- epilogue ----------------
    const int r0 = lane >> 2, c0 = (lane & 3) * 2;
#pragma unroll
    for (int mt = 0; mt < 2; mt++) {
        int mA = m0 + wm * 32 + mt * 16 + r0;
        int mB = mA + 8;
        float bvA = bias[mA], bvB = bias[mB];
#pragma unroll
        for (int nt = 0; nt < 4; nt++) {
            int n = hw0 + wn * 32 + nt * 8 + c0;
            float v0 = acc[mt][nt][0] + bvA;
            float v1 = acc[mt][nt][1] + bvA;
            float v2 = acc[mt][nt][2] + bvB;
            float v3 = acc[mt][nt][3] + bvB;
            if (ACT) { v0 = silu(v0); v1 = silu(v1); v2 = silu(v2); v3 = silu(v3); }
            size_t oA = (size_t)bz * outCtot * HW + (size_t)(coff + mA) * HW + n;
            size_t oB = (size_t)bz * outCtot * HW + (size_t)(coff + mB) * HW + n;
            if (EPI == 0) {
                *(float2*)(Yf + oA) = make_float2(v0, v1);
                *(float2*)(Yf + oB) = make_float2(v2, v3);
            } else if (EPI == 1) {
                uint32_t h, l;
                pack2(v0, v1, h, l);
                *(uint32_t*)(o1h + oA) = h; *(uint32_t*)(o1l + oA) = l;
                *(uint32_t*)(o2h + oA) = h; *(uint32_t*)(o2l + oA) = l;
                pack2(v2, v3, h, l);
                *(uint32_t*)(o1h + oB) = h; *(uint32_t*)(o1l + oB) = l;
                *(uint32_t*)(o2h + oB) = h; *(uint32_t*)(o2l + oB) = l;
            } else {
                float2 yA = *(const float2*)(Ygate + oA);
                float2 yB = *(const float2*)(Ygate + oB);
                uint32_t h, l;
                pack2(v0 * yA.x, v1 * yA.y, h, l);
                *(uint32_t*)(o1h + oA) = h; *(uint32_t*)(o1l + oA) = l;
                pack2(v2 * yB.x, v3 * yB.y, h, l);
                *(uint32_t*)(o1h + oB) = h; *(uint32_t*)(o1l + oB) = l;
            }
        }
    }
}
#define GEMM_SMEM ((2 * 2 * 128 * ASTR + 2 * 2 * 32 * BSTR) * 2)   // 59392 B

// ---------------- fused dual-branch SPPF pooling (split I/O) ---------------
__global__ void __launch_bounds__(256)
pool_both(const __nv_bfloat16* __restrict__ xh, const __nv_bfloat16* __restrict__ xl,
          __nv_bfloat16* __restrict__ o1h, __nv_bfloat16* __restrict__ o1l,
          __nv_bfloat16* __restrict__ o2h, __nv_bfloat16* __restrict__ o2l)
{
    extern __shared__ float sp[];
    float* sx = sp;
    float* si = sp + 4096;
    float* pe = sp + 8192;
    float* t1 = sp + 12288;
    float* t2 = sp + 16384;
    const int ch = blockIdx.x, b = blockIdx.y;
    const int tid = threadIdx.x;
    const size_t src = ((size_t)b * 1024 + ch) * HW;

    for (int i = tid; i < 4096; i += 256) {
        float v = __bfloat162float(xh[src + i]) + __bfloat162float(xl[src + i]);
        sx[i] = v; si[i] = v;
    }
    __syncthreads();

    for (int s = 0; s < 3; s++) {
        for (int i = tid; i < 4096; i += 256) {
            int c = i & 63;
            const float* row = &si[i - c];
            float mx = -INFINITY, sm = 0.f;
#pragma unroll
            for (int d = -2; d <= 2; d++) {
                int cc = c + d;
                if (cc >= 0 && cc < 64) { float v = row[cc]; mx = fmaxf(mx, v); sm += v; }
            }
            t1[i] = mx; t2[i] = sm;
        }
        __syncthreads();
        size_t dst = ((size_t)b * 1024 + (s + 1) * 256 + ch) * HW;
        for (int i = tid; i < 4096; i += 256) {
            int c = i & 63, r = i >> 6;
            float mx = -INFINITY, sm = 0.f;
#pragma unroll
            for (int d = -2; d <= 2; d++) {
                int rr = r + d;
                if (rr >= 0 && rr < 64) { mx = fmaxf(mx, t1[rr * 64 + c]); sm += t2[rr * 64 + c]; }
            }
            float v = 0.9f * mx + 0.004f * sm;
            si[i] = v;
            __nv_bfloat16 h = __float2bfloat16(v);
            o1h[dst + i] = h;
            o1l[dst + i] = __float2bfloat16(v - __bfloat162float(h));
        }
        __syncthreads();
    }

    for (int i = tid; i < 4096; i += 256) si[i] = sx[i];
    __syncthreads();

    for (int s = 0; s < 3; s++) {
        for (int i = tid; i < 4096; i += 256) pe[i] = __expf(si[i]);
        __syncthreads();
        for (int i = tid; i < 4096; i += 256) {
            int c = i & 63;
            const float* erow = &pe[i - c];
            const float* vrow = &si[i - c];
            float se = 0.f, sex = 0.f;
#pragma unroll
            for (int d = -2; d <= 2; d++) {
                int cc = c + d;
                if (cc >= 0 && cc < 64) {
                    float e = erow[cc];
                    se += e; sex = fmaf(e, vrow[cc], sex);
                }
            }
            t1[i] = se; t2[i] = sex;
        }
        __syncthreads();
        size_t dst = ((size_t)b * 1024 + (s + 1) * 256 + ch) * HW;
        for (int i = tid; i < 4096; i += 256) {
            int c = i & 63, r = i >> 6;
            float den = 0.f, num = 0.f;
#pragma unroll
            for (int d = -2; d <= 2; d++) {
                int rr = r + d;
                if (rr >= 0 && rr < 64) { den += t1[rr * 64 + c]; num += t2[rr * 64 + c]; }
            }
            float v = num / (den + 1e-6f);
            si[i] = v;
            __nv_bfloat16 h = __float2bfloat16(v);
            o2h[dst + i] = h;
            o2l[dst + i] = __float2bfloat16(v - __bfloat162float(h));
        }
        __syncthreads();
    }
}
#define POOL_SMEM (5 * 4096 * 4)

// ---------------- fused LSKA depthwise chain (fp32 in, split out) ----------
__global__ void __launch_bounds__(256)
dw_fused(const float* __restrict__ y,
         const float* __restrict__ w1, const float* __restrict__ b1,
         const float* __restrict__ w2, const float* __restrict__ b2,
         const float* __restrict__ w3, const float* __restrict__ b3,
         const float* __restrict__ w4, const float* __restrict__ b4,
         __nv_bfloat16* __restrict__ oh, __nv_bfloat16* __restrict__ ol)
{
    __shared__ float s0[4096], s1[4096];
    const int ch = blockIdx.x, b = blockIdx.y;
    const int tid = threadIdx.x;
    const size_t off = ((size_t)b * 1024 + ch) * HW;

    for (int i = tid; i < 4096; i += 256) s0[i] = y[off + i];
    __syncthreads();

    {
        float wa = w1[ch * 3], wb = w1[ch * 3 + 1], wc = w1[ch * 3 + 2], bb = b1[ch];
        for (int i = tid; i < 4096; i += 256) {
            int c = i & 63;
            const float* row = &s0[i - c];
            float acc = bb + wb * row[c];
            if (c >= 1)  acc = fmaf(wa, row[c - 1], acc);
            if (c <= 62) acc = fmaf(wc, row[c + 1], acc);
            s1[i] = acc;
        }
    }
    __syncthreads();
    {
        float wa = w2[ch * 3], wb = w2[ch * 3 + 1], wc = w2[ch * 3 + 2], bb = b2[ch];
        for (int i = tid; i < 4096; i += 256) {
            int r = i >> 6;
            float acc = bb + wb * s1[i];
            if (r >= 1)  acc = fmaf(wa, s1[i - 64], acc);
            if (r <= 62) acc = fmaf(wc, s1[i + 64], acc);
            s0[i] = acc;
        }
    }
    __syncthreads();
    {
        float wa = w3[ch * 3], wb = w3[ch * 3 + 1], wc = w3[ch * 3 + 2], bb = b3[ch];
        for (int i = tid; i < 4096; i += 256) {
            int c = i & 63;
            const float* row = &s0[i - c];
            float acc = bb + wb * row[c];
            if (c >= 2)  acc = fmaf(wa, row[c - 2], acc);
            if (c <= 61) acc = fmaf(wc, row[c + 2], acc);
            s1[i] = acc;
        }
    }
    __syncthreads();
    {
        float wa = w4[ch * 3], wb = w4[ch * 3 + 1], wc = w4[ch * 3 + 2], bb = b4[ch];
        for (int i = tid; i < 4096; i += 256) {
            int r = i >> 6;
            float acc = bb + wb * s1[i];
            if (r >= 2)  acc = fmaf(wa, s1[i - 128], acc);
            if (r <= 61) acc = fmaf(wc, s1[i + 128], acc);
            __nv_bfloat16 h = __float2bfloat16(acc);
            oh[off + i] = h;
            ol[off + i] = __float2bfloat16(acc - __bfloat162float(h));
        }
    }
}

// ---------------- launch ----------------------------------------------------
extern "C" void kernel_launch(void* const* d_in, const int* in_sizes, int n_in,
                              void* d_out, int out_size)
{
    const float* x       = (const float*)d_in[0];
    const float* w_sta   = (const float*)d_in[1];
    const float* b_sta   = (const float*)d_in[2];
    const float* w_cv1   = (const float*)d_in[3];
    const float* b_cv1   = (const float*)d_in[4];
    const float* w_cv2   = (const float*)d_in[5];
    const float* b_cv2   = (const float*)d_in[6];
    const float* w_cvend = (const float*)d_in[7];
    const float* b_cvend = (const float*)d_in[8];
    const float* w_dwh   = (const float*)d_in[9];
    const float* b_dwh   = (const float*)d_in[10];
    const float* w_dwv   = (const float*)d_in[11];
    const float* b_dwv   = (const float*)d_in[12];
    const float* w_ddwh  = (const float*)d_in[13];
    const float* b_ddwh  = (const float*)d_in[14];
    const float* w_ddwv  = (const float*)d_in[15];
    const float* b_ddwv  = (const float*)d_in[16];
    const float* w_c1    = (const float*)d_in[17];
    const float* b_c1    = (const float*)d_in[18];

    float *y;
    __nv_bfloat16 *x0h, *x0l, *xh1, *xl1, *xh2, *xl2, *bh, *bl, *gh, *gl;
    __nv_bfloat16 *wsh, *wsl, *w1h, *w1l, *w2h, *w2l, *weh, *wel, *wch, *wcl;
    cudaGetSymbolAddress((void**)&y,   g_y);
    cudaGetSymbolAddress((void**)&x0h, g_x0h); cudaGetSymbolAddress((void**)&x0l, g_x0l);
    cudaGetSymbolAddress((void**)&xh1, g_xh1); cudaGetSymbolAddress((void**)&xl1, g_xl1);
    cudaGetSymbolAddress((void**)&xh2, g_xh2); cudaGetSymbolAddress((void**)&xl2, g_xl2);
    cudaGetSymbolAddress((void**)&bh,  g_bh);  cudaGetSymbolAddress((void**)&bl,  g_bl);
    cudaGetSymbolAddress((void**)&gh,  g_gh);  cudaGetSymbolAddress((void**)&gl,  g_gl);
    cudaGetSymbolAddress((void**)&wsh, g_wsh); cudaGetSymbolAddress((void**)&wsl, g_wsl);
    cudaGetSymbolAddress((void**)&w1h, g_w1h); cudaGetSymbolAddress((void**)&w1l, g_w1l);
    cudaGetSymbolAddress((void**)&w2h, g_w2h); cudaGetSymbolAddress((void**)&w2l, g_w2l);
    cudaGetSymbolAddress((void**)&weh, g_weh); cudaGetSymbolAddress((void**)&wel, g_wel);
    cudaGetSymbolAddress((void**)&wch, g_wch); cudaGetSymbolAddress((void**)&wcl, g_wcl);

    cudaFuncSetAttribute(gemm_pre<1, 1>, cudaFuncAttributeMaxDynamicSharedMemorySize, GEMM_SMEM);
    cudaFuncSetAttribute(gemm_pre<1, 0>, cudaFuncAttributeMaxDynamicSharedMemorySize, GEMM_SMEM);
    cudaFuncSetAttribute(gemm_pre<0, 2>, cudaFuncAttributeMaxDynamicSharedMemorySize, GEMM_SMEM);
    cudaFuncSetAttribute(pool_both, cudaFuncAttributeMaxDynamicSharedMemorySize, POOL_SMEM);
    auto g4 = [](int n) { return (n / 4 + 255) / 256; };

    // launch order arranged so ncu (-s 5 -c 1) captures the cv1 GEMM (launch #6)
    // 1) split input
    split2<<<g4(NB * 512 * HW), 256>>>(x, x0h, x0l, NB * 512 * HW / 4);
    // 2) split sta weight
    split2<<<g4(256 * 512), 256>>>(w_sta, wsh, wsl, 256 * 512 / 4);
    // 3) sta: 512->256 + SiLU, split-dup into (xh1,xl1)/(xh2,xl2) ch 0..255
    gemm_pre<1, 1><<<dim3(2, 64, NB), 256, GEMM_SMEM>>>(
        wsh, wsl, x0h, x0l, b_sta, nullptr, nullptr, xh1, xl1, xh2, xl2, 512, 1024, 0);
    // 4) fused dual-branch pooling (ch 256..1023)
    pool_both<<<dim3(256, NB), 256, POOL_SMEM>>>(xh1, xl1, xh1, xl1, xh2, xl2);
    // 5) split cv1 weight
    split2<<<g4(512 * 1024), 256>>>(w_cv1, w1h, w1l, 512 * 1024 / 4);
    // 6) cv1: 1024->512 + SiLU -> y[0:512]   <-- ncu capture slot
    gemm_pre<1, 0><<<dim3(4, 64, NB), 256, GEMM_SMEM>>>(
        w1h, w1l, xh1, xl1, b_cv1, y, nullptr, nullptr, nullptr, nullptr, nullptr, 1024, 1024, 0);
    // 7) split cv2 weight, 8) cv2 -> y[512:1024]
    split2<<<g4(512 * 1024), 256>>>(w_cv2, w2h, w2l, 512 * 1024 / 4);
    gemm_pre<1, 0><<<dim3(4, 64, NB), 256, GEMM_SMEM>>>(
        w2h, w2l, xh2, xl2, b_cv2, y, nullptr, nullptr, nullptr, nullptr, nullptr, 1024, 1024, 512);
    // 9) fused LSKA depthwise chain: y -> split (bh,bl)
    dw_fused<<<dim3(1024, NB), 256>>>(y, w_dwh, b_dwh, w_dwv, b_dwv,
                                      w_ddwh, b_ddwh, w_ddwv, b_ddwv, bh, bl);
    // 10) split c1 weight, 11) c1 (gate fused) -> (gh,gl)
    split2<<<g4(1024 * 1024), 256>>>(w_c1, wch, wcl, 1024 * 1024 / 4);
    gemm_pre<0, 2><<<dim3(8, 64, NB), 256, GEMM_SMEM>>>(
        wch, wcl, bh, bl, b_c1, nullptr, y, gh, gl, nullptr, nullptr, 1024, 1024, 0);
    // 12) split cvend weight, 13) cvend -> output
    split2<<<g4(512 * 1024), 256>>>(w_cvend, weh, wel, 512 * 1024 / 4);
    gemm_pre<1, 0><<<dim3(4, 64, NB), 256, GEMM_SMEM>>>(
        weh, wel, gh, gl, b_cvend, (float*)d_out, nullptr, nullptr, nullptr, nullptr, nullptr,
        1024, 512, 0);
}

// round 16
// speedup vs baseline: 1.2327x; 1.0394x over previous
#include <cuda_runtime.h>
#include <cuda_bf16.h>
#include <math.h>
#include <stdint.h>

#define HW 4096
#define NB 8
#define ASTR 40       // A smem row stride (halves): 32 + 8 pad
#define BSTR 72       // B smem row stride (halves): 64 + 8 pad

// ---------------- scratch (device globals) ---------------------------------
__device__ float g_y[NB * 1024 * HW];                       // concat(cv1,cv2) fp32
__device__ __nv_bfloat16 g_x0h[NB * 512 * HW], g_x0l[NB * 512 * HW];     // split input x
__device__ __nv_bfloat16 g_xh1[NB * 1024 * HW], g_xl1[NB * 1024 * HW];   // cv1 input
__device__ __nv_bfloat16 g_xh2[NB * 1024 * HW], g_xl2[NB * 1024 * HW];   // cv2 input
__device__ __nv_bfloat16 g_bh [NB * 1024 * HW], g_bl [NB * 1024 * HW];   // c1 input (dw out)
__device__ __nv_bfloat16 g_gh [NB * 1024 * HW], g_gl [NB * 1024 * HW];   // cvend input (gated)
__device__ __nv_bfloat16 g_wsh[256 * 512],   g_wsl[256 * 512];
__device__ __nv_bfloat16 g_w1h[512 * 1024],  g_w1l[512 * 1024];
__device__ __nv_bfloat16 g_w2h[512 * 1024],  g_w2l[512 * 1024];
__device__ __nv_bfloat16 g_weh[512 * 1024],  g_wel[512 * 1024];
__device__ __nv_bfloat16 g_wch[1024 * 1024], g_wcl[1024 * 1024];

// ---------------- helpers ---------------------------------------------------
__device__ __forceinline__ void ldsm4(unsigned* r, const __nv_bfloat16* p) {
    unsigned a = (unsigned)__cvta_generic_to_shared(p);
    asm volatile("ldmatrix.sync.aligned.m8n8.x4.shared.b16 {%0,%1,%2,%3},[%4];"
        : "=r"(r[0]), "=r"(r[1]), "=r"(r[2]), "=r"(r[3]) : "r"(a));
}
__device__ __forceinline__ void ldsm4t(unsigned* r, const __nv_bfloat16* p) {
    unsigned a = (unsigned)__cvta_generic_to_shared(p);
    asm volatile("ldmatrix.sync.aligned.m8n8.x4.trans.shared.b16 {%0,%1,%2,%3},[%4];"
        : "=r"(r[0]), "=r"(r[1]), "=r"(r[2]), "=r"(r[3]) : "r"(a));
}
__device__ __forceinline__ void mma16816(float* d, const unsigned* a, const unsigned* b) {
    asm volatile("mma.sync.aligned.m16n8k16.row.col.f32.bf16.bf16.f32 "
        "{%0,%1,%2,%3},{%4,%5,%6,%7},{%8,%9},{%0,%1,%2,%3};"
        : "+f"(d[0]), "+f"(d[1]), "+f"(d[2]), "+f"(d[3])
        : "r"(a[0]), "r"(a[1]), "r"(a[2]), "r"(a[3]), "r"(b[0]), "r"(b[1]));
}
__device__ __forceinline__ void pack2(float a, float b, uint32_t& h, uint32_t& l) {
    __nv_bfloat16 ha = __float2bfloat16(a), hb = __float2bfloat16(b);
    __nv_bfloat162 hp(ha, hb);
    __nv_bfloat162 lp(__float2bfloat16(a - __bfloat162float(ha)),
                      __float2bfloat16(b - __bfloat162float(hb)));
    h = *(uint32_t*)&hp; l = *(uint32_t*)&lp;
}
__device__ __forceinline__ float silu(float v) { return v / (1.f + __expf(-v)); }

// ---------------- fp32 -> bf16 hi/lo split ---------------------------------
__global__ void split2(const float* __restrict__ in, __nv_bfloat16* __restrict__ hi,
                       __nv_bfloat16* __restrict__ lo, int n4)
{
    int i = blockIdx.x * blockDim.x + threadIdx.x;
    if (i >= n4) return;
    float4 v = ((const float4*)in)[i];
    uint32_t h0, l0, h1, l1;
    pack2(v.x, v.y, h0, l0);
    pack2(v.z, v.w, h1, l1);
    ((uint32_t*)hi)[i * 2] = h0;     ((uint32_t*)hi)[i * 2 + 1] = h1;
    ((uint32_t*)lo)[i * 2] = l0;     ((uint32_t*)lo)[i * 2 + 1] = l1;
}

// ---------------- GEMM: 128x64x32 tile, 2 CTAs/SM (R15, unchanged) ---------
template<int ACT, int EPI>
__global__ void __launch_bounds__(256, 2)
gemm_pre(const __nv_bfloat16* __restrict__ Ahi, const __nv_bfloat16* __restrict__ Alo,
         const __nv_bfloat16* __restrict__ Bhi, const __nv_bfloat16* __restrict__ Blo,
         const float* __restrict__ bias, float* __restrict__ Yf,
         const float* __restrict__ Ygate,
         __nv_bfloat16* __restrict__ o1h, __nv_bfloat16* __restrict__ o1l,
         __nv_bfloat16* __restrict__ o2h, __nv_bfloat16* __restrict__ o2l,
         int K, int outCtot, int coff)
{
    extern __shared__ __align__(16) char smraw[];
    __nv_bfloat16* sA = (__nv_bfloat16*)smraw;                 // [2 par][2 spl][128][ASTR]
    __nv_bfloat16* sB = sA + 2 * 2 * 128 * ASTR;               // [2 par][2 spl][32][BSTR]

    const int tid = threadIdx.x;
    const int lane = tid & 31, warp = tid >> 5;
    const int wm = warp >> 1, wn = warp & 1;   // 4 x 2 warp grid
    const int m0 = blockIdx.x * 128;
    const int hw0 = blockIdx.y * 64;
    const int bz = blockIdx.z;
    const size_t xoff = (size_t)bz * K * HW;
    const int iters = K / 32;

    int aRow[2], aKg[2];
#pragma unroll
    for (int e = 0; e < 2; e++) {
        int i = tid + e * 256;
        aRow[e] = i >> 2;  aKg[e] = (i & 3) * 8;
    }
    const int bKr = tid >> 3, bNg = (tid & 7) * 8;

    uint4 rah[2], ral[2], rbh, rbl;
    auto loadRegs = [&](int it) {
        int k0 = it * 32;
#pragma unroll
        for (int e = 0; e < 2; e++) {
            size_t ga = (size_t)(m0 + aRow[e]) * K + k0 + aKg[e];
            rah[e] = *(const uint4*)(Ahi + ga);
            ral[e] = *(const uint4*)(Alo + ga);
        }
        size_t gb = xoff + (size_t)(k0 + bKr) * HW + hw0 + bNg;
        rbh = *(const uint4*)(Bhi + gb);
        rbl = *(const uint4*)(Blo + gb);
    };
    auto stsRegs = [&](int p) {
#pragma unroll
        for (int e = 0; e < 2; e++) {
            *(uint4*)(sA + ((p * 2 + 0) * 128 + aRow[e]) * ASTR + aKg[e]) = rah[e];
            *(uint4*)(sA + ((p * 2 + 1) * 128 + aRow[e]) * ASTR + aKg[e]) = ral[e];
        }
        *(uint4*)(sB + ((p * 2 + 0) * 32 + bKr) * BSTR + bNg) = rbh;
        *(uint4*)(sB + ((p * 2 + 1) * 32 + bKr) * BSTR + bNg) = rbl;
    };

    float acc[2][4][4];
#pragma unroll
    for (int i = 0; i < 2; i++)
#pragma unroll
        for (int j = 0; j < 4; j++)
#pragma unroll
            for (int q = 0; q < 4; q++) acc[i][j][q] = 0.f;

    const int arow = lane & 15;
    const int acol8 = (lane >> 4) << 3;
    const int bkrow = (lane & 7) + ((lane & 8) ? 8 : 0);
    const int bcol8 = (lane & 16) ? 8 : 0;

    loadRegs(0);
    stsRegs(0);
    if (iters > 1) loadRegs(1);
    __syncthreads();

    int p = 0;
    for (int it = 0; it < iters; it++) {
        if (it + 1 < iters) stsRegs(p ^ 1);
        if (it + 2 < iters) loadRegs(it + 2);

#pragma unroll
        for (int ks = 0; ks < 2; ks++) {
            unsigned ah[2][4], al[2][4], bh[4][2], bl[4][2];
            const int acol = ks * 16 + acol8;
#pragma unroll
            for (int mt = 0; mt < 2; mt++) {
                int m = wm * 32 + mt * 16 + arow;
                ldsm4(ah[mt], sA + ((p * 2 + 0) * 128 + m) * ASTR + acol);
                ldsm4(al[mt], sA + ((p * 2 + 1) * 128 + m) * ASTR + acol);
            }
            const int krow = ks * 16 + bkrow;
#pragma unroll
            for (int q = 0; q < 2; q++) {
                int j0 = wn * 32 + q * 16 + bcol8;
                unsigned r[4];
                ldsm4t(r, sB + ((p * 2 + 0) * 32 + krow) * BSTR + j0);
                bh[q * 2][0] = r[0]; bh[q * 2][1] = r[1];
                bh[q * 2 + 1][0] = r[2]; bh[q * 2 + 1][1] = r[3];
                ldsm4t(r, sB + ((p * 2 + 1) * 32 + krow) * BSTR + j0);
                bl[q * 2][0] = r[0]; bl[q * 2][1] = r[1];
                bl[q * 2 + 1][0] = r[2]; bl[q * 2 + 1][1] = r[3];
            }
#pragma unroll
            for (int mt = 0; mt < 2; mt++)
#pragma unroll
                for (int nt = 0; nt < 4; nt++) {
                    mma16816(acc[mt][nt], ah[mt], bh[nt]);
                    mma16816(acc[mt][nt], ah[mt], bl[nt]);
                    mma16816(acc[mt][nt], al[mt], bh[nt]);
                }
        }
        __syncthreads();
        p ^= 1;
    }

    const int r0 = lane >> 2, c0 = (lane & 3) * 2;
#pragma unroll
    for (int mt = 0; mt < 2; mt++) {
        int mA = m0 + wm * 32 + mt * 16 + r0;
        int mB = mA + 8;
        float bvA = bias[mA], bvB = bias[mB];
#pragma unroll
        for (int nt = 0; nt < 4; nt++) {
            int n = hw0 + wn * 32 + nt * 8 + c0;
            float v0 = acc[mt][nt][0] + bvA;
            float v1 = acc[mt][nt][1] + bvA;
            float v2 = acc[mt][nt][2] + bvB;
            float v3 = acc[mt][nt][3] + bvB;
            if (ACT) { v0 = silu(v0); v1 = silu(v1); v2 = silu(v2); v3 = silu(v3); }
            size_t oA = (size_t)bz * outCtot * HW + (size_t)(coff + mA) * HW + n;
            size_t oB = (size_t)bz * outCtot * HW + (size_t)(coff + mB) * HW + n;
            if (EPI == 0) {
                *(float2*)(Yf + oA) = make_float2(v0, v1);
                *(float2*)(Yf + oB) = make_float2(v2, v3);
            } else if (EPI == 1) {
                uint32_t h, l;
                pack2(v0, v1, h, l);
                *(uint32_t*)(o1h + oA) = h; *(uint32_t*)(o1l + oA) = l;
                *(uint32_t*)(o2h + oA) = h; *(uint32_t*)(o2l + oA) = l;
                pack2(v2, v3, h, l);
                *(uint32_t*)(o1h + oB) = h; *(uint32_t*)(o1l + oB) = l;
                *(uint32_t*)(o2h + oB) = h; *(uint32_t*)(o2l + oB) = l;
            } else {
                float2 yA = *(const float2*)(Ygate + oA);
                float2 yB = *(const float2*)(Ygate + oB);
                uint32_t h, l;
                pack2(v0 * yA.x, v1 * yA.y, h, l);
                *(uint32_t*)(o1h + oA) = h; *(uint32_t*)(o1l + oA) = l;
                pack2(v2 * yB.x, v3 * yB.y, h, l);
                *(uint32_t*)(o1h + oB) = h; *(uint32_t*)(o1l + oB) = l;
            }
        }
    }
}
#define GEMM_SMEM ((2 * 2 * 128 * ASTR + 2 * 2 * 32 * BSTR) * 2)   // 59392 B

// ---------------- fused dual-branch SPPF pooling: 512 thr, 4 planes --------
__global__ void __launch_bounds__(512)
pool_both(const __nv_bfloat16* __restrict__ xh, const __nv_bfloat16* __restrict__ xl,
          __nv_bfloat16* __restrict__ o1h, __nv_bfloat16* __restrict__ o1l,
          __nv_bfloat16* __restrict__ o2h, __nv_bfloat16* __restrict__ o2l)
{
    extern __shared__ float sp[];
    float* si = sp;            // working value plane
    float* pe = sp + 4096;     // exp plane (branch 2 only)
    float* t1 = sp + 8192;
    float* t2 = sp + 12288;
    const int ch = blockIdx.x, b = blockIdx.y;
    const int tid = threadIdx.x;
    const size_t src = ((size_t)b * 1024 + ch) * HW;

    for (int i = tid; i < 4096; i += 512)
        si[i] = __bfloat162float(xh[src + i]) + __bfloat162float(xl[src + i]);
    __syncthreads();

    // branch 1: TMaxAvg cascades
    for (int s = 0; s < 3; s++) {
        for (int i = tid; i < 4096; i += 512) {
            int c = i & 63;
            const float* row = &si[i - c];
            float mx = -INFINITY, sm = 0.f;
#pragma unroll
            for (int d = -2; d <= 2; d++) {
                int cc = c + d;
                if (cc >= 0 && cc < 64) { float v = row[cc]; mx = fmaxf(mx, v); sm += v; }
            }
            t1[i] = mx; t2[i] = sm;
        }
        __syncthreads();
        size_t dst = ((size_t)b * 1024 + (s + 1) * 256 + ch) * HW;
        for (int i = tid; i < 4096; i += 512) {
            int c = i & 63, r = i >> 6;
            float mx = -INFINITY, sm = 0.f;
#pragma unroll
            for (int d = -2; d <= 2; d++) {
                int rr = r + d;
                if (rr >= 0 && rr < 64) { mx = fmaxf(mx, t1[rr * 64 + c]); sm += t2[rr * 64 + c]; }
            }
            float v = 0.9f * mx + 0.004f * sm;
            si[i] = v;
            __nv_bfloat16 h = __float2bfloat16(v);
            o1h[dst + i] = h;
            o1l[dst + i] = __float2bfloat16(v - __bfloat162float(h));
        }
        __syncthreads();
    }

    // reload pristine input for branch 2 (L2-warm)
    for (int i = tid; i < 4096; i += 512)
        si[i] = __bfloat162float(xh[src + i]) + __bfloat162float(xl[src + i]);
    __syncthreads();

    // branch 2: RWPool cascades
    for (int s = 0; s < 3; s++) {
        for (int i = tid; i < 4096; i += 512) pe[i] = __expf(si[i]);
        __syncthreads();
        for (int i = tid; i < 4096; i += 512) {
            int c = i & 63;
            const float* erow = &pe[i - c];
            const float* vrow = &si[i - c];
            float se = 0.f, sex = 0.f;
#pragma unroll
            for (int d = -2; d <= 2; d++) {
                int cc = c + d;
                if (cc >= 0 && cc < 64) {
                    float e = erow[cc];
                    se += e; sex = fmaf(e, vrow[cc], sex);
                }
            }
            t1[i] = se; t2[i] = sex;
        }
        __syncthreads();
        size_t dst = ((size_t)b * 1024 + (s + 1) * 256 + ch) * HW;
        for (int i = tid; i < 4096; i += 512) {
            int c = i & 63, r = i >> 6;
            float den = 0.f, num = 0.f;
#pragma unroll
            for (int d = -2; d <= 2; d++) {
                int rr = r + d;
                if (rr >= 0 && rr < 64) { den += t1[rr * 64 + c]; num += t2[rr * 64 + c]; }
            }
            float v = num / (den + 1e-6f);
            si[i] = v;
            __nv_bfloat16 h = __float2bfloat16(v);
            o2h[dst + i] = h;
            o2l[dst + i] = __float2bfloat16(v - __bfloat162float(h));
        }
        __syncthreads();
    }
}
#define POOL_SMEM (4 * 4096 * 4)   // 65536 B -> 3 CTAs/SM

// ---------------- fused LSKA depthwise chain: 512 threads ------------------
__global__ void __launch_bounds__(512)
dw_fused(const float* __restrict__ y,
         const float* __restrict__ w1, const float* __restrict__ b1,
         const float* __restrict__ w2, const float* __restrict__ b2,
         const float* __restrict__ w3, const float* __restrict__ b3,
         const float* __restrict__ w4, const float* __restrict__ b4,
         __nv_bfloat16* __restrict__ oh, __nv_bfloat16* __restrict__ ol)
{
    __shared__ float s0[4096], s1[4096];
    const int ch = blockIdx.x, b = blockIdx.y;
    const int tid = threadIdx.x;
    const size_t off = ((size_t)b * 1024 + ch) * HW;

    for (int i = tid; i < 4096; i += 512) s0[i] = y[off + i];
    __syncthreads();

    {
        float wa = w1[ch * 3], wb = w1[ch * 3 + 1], wc = w1[ch * 3 + 2], bb = b1[ch];
        for (int i = tid; i < 4096; i += 512) {
            int c = i & 63;
            const float* row = &s0[i - c];
            float acc = bb + wb * row[c];
            if (c >= 1)  acc = fmaf(wa, row[c - 1], acc);
            if (c <= 62) acc = fmaf(wc, row[c + 1], acc);
            s1[i] = acc;
        }
    }
    __syncthreads();
    {
        float wa = w2[ch * 3], wb = w2[ch * 3 + 1], wc = w2[ch * 3 + 2], bb = b2[ch];
        for (int i = tid; i < 4096; i += 512) {
            int r = i >> 6;
            float acc = bb + wb * s1[i];
            if (r >= 1)  acc = fmaf(wa, s1[i - 64], acc);
            if (r <= 62) acc = fmaf(wc, s1[i + 64], acc);
            s0[i] = acc;
        }
    }
    __syncthreads();
    {
        float wa = w3[ch * 3], wb = w3[ch * 3 + 1], wc = w3[ch * 3 + 2], bb = b3[ch];
        for (int i = tid; i < 4096; i += 512) {
            int c = i & 63;
            const float* row = &s0[i - c];
            float acc = bb + wb * row[c];
            if (c >= 2)  acc = fmaf(wa, row[c - 2], acc);
            if (c <= 61) acc = fmaf(wc, row[c + 2], acc);
            s1[i] = acc;
        }
    }
    __syncthreads();
    {
        float wa = w4[ch * 3], wb = w4[ch * 3 + 1], wc = w4[ch * 3 + 2], bb = b4[ch];
        for (int i = tid; i < 4096; i += 512) {
            int r = i >> 6;
            float acc = bb + wb * s1[i];
            if (r >= 2)  acc = fmaf(wa, s1[i - 128], acc);
            if (r <= 61) acc = fmaf(wc, s1[i + 128], acc);
            __nv_bfloat16 h = __float2bfloat16(acc);
            oh[off + i] = h;
            ol[off + i] = __float2bfloat16(acc - __bfloat162float(h));
        }
    }
}

// ---------------- launch ----------------------------------------------------
extern "C" void kernel_launch(void* const* d_in, const int* in_sizes, int n_in,
                              void* d_out, int out_size)
{
    const float* x       = (const float*)d_in[0];
    const float* w_sta   = (const float*)d_in[1];
    const float* b_sta   = (const float*)d_in[2];
    const float* w_cv1   = (const float*)d_in[3];
    const float* b_cv1   = (const float*)d_in[4];
    const float* w_cv2   = (const float*)d_in[5];
    const float* b_cv2   = (const float*)d_in[6];
    const float* w_cvend = (const float*)d_in[7];
    const float* b_cvend = (const float*)d_in[8];
    const float* w_dwh   = (const float*)d_in[9];
    const float* b_dwh   = (const float*)d_in[10];
    const float* w_dwv   = (const float*)d_in[11];
    const float* b_dwv   = (const float*)d_in[12];
    const float* w_ddwh  = (const float*)d_in[13];
    const float* b_ddwh  = (const float*)d_in[14];
    const float* w_ddwv  = (const float*)d_in[15];
    const float* b_ddwv  = (const float*)d_in[16];
    const float* w_c1    = (const float*)d_in[17];
    const float* b_c1    = (const float*)d_in[18];

    float *y;
    __nv_bfloat16 *x0h, *x0l, *xh1, *xl1, *xh2, *xl2, *bh, *bl, *gh, *gl;
    __nv_bfloat16 *wsh, *wsl, *w1h, *w1l, *w2h, *w2l, *weh, *wel, *wch, *wcl;
    cudaGetSymbolAddress((void**)&y,   g_y);
    cudaGetSymbolAddress((void**)&x0h, g_x0h); cudaGetSymbolAddress((void**)&x0l, g_x0l);
    cudaGetSymbolAddress((void**)&xh1, g_xh1); cudaGetSymbolAddress((void**)&xl1, g_xl1);
    cudaGetSymbolAddress((void**)&xh2, g_xh2); cudaGetSymbolAddress((void**)&xl2, g_xl2);
    cudaGetSymbolAddress((void**)&bh,  g_bh);  cudaGetSymbolAddress((void**)&bl,  g_bl);
    cudaGetSymbolAddress((void**)&gh,  g_gh);  cudaGetSymbolAddress((void**)&gl,  g_gl);
    cudaGetSymbolAddress((void**)&wsh, g_wsh); cudaGetSymbolAddress((void**)&wsl, g_wsl);
    cudaGetSymbolAddress((void**)&w1h, g_w1h); cudaGetSymbolAddress((void**)&w1l, g_w1l);
    cudaGetSymbolAddress((void**)&w2h, g_w2h); cudaGetSymbolAddress((void**)&w2l, g_w2l);
    cudaGetSymbolAddress((void**)&weh, g_weh); cudaGetSymbolAddress((void**)&wel, g_wel);
    cudaGetSymbolAddress((void**)&wch, g_wch); cudaGetSymbolAddress((void**)&wcl, g_wcl);

    cudaFuncSetAttribute(gemm_pre<1, 1>, cudaFuncAttributeMaxDynamicSharedMemorySize, GEMM_SMEM);
    cudaFuncSetAttribute(gemm_pre<1, 0>, cudaFuncAttributeMaxDynamicSharedMemorySize, GEMM_SMEM);
    cudaFuncSetAttribute(gemm_pre<0, 2>, cudaFuncAttributeMaxDynamicSharedMemorySize, GEMM_SMEM);
    cudaFuncSetAttribute(pool_both, cudaFuncAttributeMaxDynamicSharedMemorySize, POOL_SMEM);
    auto g4 = [](int n) { return (n / 4 + 255) / 256; };

    // 1) split input
    split2<<<g4(NB * 512 * HW), 256>>>(x, x0h, x0l, NB * 512 * HW / 4);
    // 2) split sta weight
    split2<<<g4(256 * 512), 256>>>(w_sta, wsh, wsl, 256 * 512 / 4);
    // 3) sta: 512->256 + SiLU, split-dup into (xh1,xl1)/(xh2,xl2) ch 0..255
    gemm_pre<1, 1><<<dim3(2, 64, NB), 256, GEMM_SMEM>>>(
        wsh, wsl, x0h, x0l, b_sta, nullptr, nullptr, xh1, xl1, xh2, xl2, 512, 1024, 0);
    // 4) fused dual-branch pooling (ch 256..1023)
    pool_both<<<dim3(256, NB), 512, POOL_SMEM>>>(xh1, xl1, xh1, xl1, xh2, xl2);
    // 5) split cv1 weight
    split2<<<g4(512 * 1024), 256>>>(w_cv1, w1h, w1l, 512 * 1024 / 4);
    // 6) cv1: 1024->512 + SiLU -> y[0:512]
    gemm_pre<1, 0><<<dim3(4, 64, NB), 256, GEMM_SMEM>>>(
        w1h, w1l, xh1, xl1, b_cv1, y, nullptr, nullptr, nullptr, nullptr, nullptr, 1024, 1024, 0);
    // 7) split cv2 weight, 8) cv2 -> y[512:1024]
    split2<<<g4(512 * 1024), 256>>>(w_cv2, w2h, w2l, 512 * 1024 / 4);
    gemm_pre<1, 0><<<dim3(4, 64, NB), 256, GEMM_SMEM>>>(
        w2h, w2l, xh2, xl2, b_cv2, y, nullptr, nullptr, nullptr, nullptr, nullptr, 1024, 1024, 512);
    // 9) fused LSKA depthwise chain: y -> split (bh,bl)
    dw_fused<<<dim3(1024, NB), 512>>>(y, w_dwh, b_dwh, w_dwv, b_dwv,
                                      w_ddwh, b_ddwh, w_ddwv, b_ddwv, bh, bl);
    // 10) split c1 weight, 11) c1 (gate fused) -> (gh,gl)
    split2<<<g4(1024 * 1024), 256>>>(w_c1, wch, wcl, 1024 * 1024 / 4);
    gemm_pre<0, 2><<<dim3(8, 64, NB), 256, GEMM_SMEM>>>(
        wch, wcl, bh, bl, b_c1, nullptr, y, gh, gl, nullptr, nullptr, 1024, 1024, 0);
    // 12) split cvend weight, 13) cvend -> output
    split2<<<g4(512 * 1024), 256>>>(w_cvend, weh, wel, 512 * 1024 / 4);
    gemm_pre<1, 0><<<dim3(4, 64, NB), 256, GEMM_SMEM>>>(
        weh, wel, gh, gl, b_cvend, (float*)d_out, nullptr, nullptr, nullptr, nullptr, nullptr,
        1024, 512, 0);
}

// round 17
// speedup vs baseline: 1.2603x; 1.0224x over previous
#include <cuda_runtime.h>
#include <cuda_bf16.h>
#include <math.h>
#include <stdint.h>

#define HW 4096
#define NB 8
#define ASTR 40       // A smem row stride (halves): 32 + 8 pad
#define BSTR 72       // B smem row stride (halves): 64 + 8 pad

// ---------------- scratch (device globals) ---------------------------------
__device__ float g_y[NB * 1024 * HW];                       // concat(cv1,cv2) fp32
__device__ __nv_bfloat16 g_x0h[NB * 512 * HW], g_x0l[NB * 512 * HW];     // split input x
__device__ __nv_bfloat16 g_xh1[NB * 1024 * HW], g_xl1[NB * 1024 * HW];   // cv1 input
__device__ __nv_bfloat16 g_xh2[NB * 1024 * HW], g_xl2[NB * 1024 * HW];   // cv2 input
__device__ __nv_bfloat16 g_bh [NB * 1024 * HW], g_bl [NB * 1024 * HW];   // c1 input (dw out)
__device__ __nv_bfloat16 g_gh [NB * 1024 * HW], g_gl [NB * 1024 * HW];   // cvend input (gated)
__device__ __nv_bfloat16 g_wsh[256 * 512],   g_wsl[256 * 512];
__device__ __nv_bfloat16 g_w1h[512 * 1024],  g_w1l[512 * 1024];
__device__ __nv_bfloat16 g_w2h[512 * 1024],  g_w2l[512 * 1024];
__device__ __nv_bfloat16 g_weh[512 * 1024],  g_wel[512 * 1024];
__device__ __nv_bfloat16 g_wch[1024 * 1024], g_wcl[1024 * 1024];

// ---------------- helpers ---------------------------------------------------
__device__ __forceinline__ void ldsm4(unsigned* r, const __nv_bfloat16* p) {
    unsigned a = (unsigned)__cvta_generic_to_shared(p);
    asm volatile("ldmatrix.sync.aligned.m8n8.x4.shared.b16 {%0,%1,%2,%3},[%4];"
        : "=r"(r[0]), "=r"(r[1]), "=r"(r[2]), "=r"(r[3]) : "r"(a));
}
__device__ __forceinline__ void ldsm4t(unsigned* r, const __nv_bfloat16* p) {
    unsigned a = (unsigned)__cvta_generic_to_shared(p);
    asm volatile("ldmatrix.sync.aligned.m8n8.x4.trans.shared.b16 {%0,%1,%2,%3},[%4];"
        : "=r"(r[0]), "=r"(r[1]), "=r"(r[2]), "=r"(r[3]) : "r"(a));
}
__device__ __forceinline__ void mma16816(float* d, const unsigned* a, const unsigned* b) {
    asm volatile("mma.sync.aligned.m16n8k16.row.col.f32.bf16.bf16.f32 "
        "{%0,%1,%2,%3},{%4,%5,%6,%7},{%8,%9},{%0,%1,%2,%3};"
        : "+f"(d[0]), "+f"(d[1]), "+f"(d[2]), "+f"(d[3])
        : "r"(a[0]), "r"(a[1]), "r"(a[2]), "r"(a[3]), "r"(b[0]), "r"(b[1]));
}
__device__ __forceinline__ void pack2(float a, float b, uint32_t& h, uint32_t& l) {
    __nv_bfloat16 ha = __float2bfloat16(a), hb = __float2bfloat16(b);
    __nv_bfloat162 hp(ha, hb);
    __nv_bfloat162 lp(__float2bfloat16(a - __bfloat162float(ha)),
                      __float2bfloat16(b - __bfloat162float(hb)));
    h = *(uint32_t*)&hp; l = *(uint32_t*)&lp;
}
__device__ __forceinline__ float silu(float v) { return v / (1.f + __expf(-v)); }

// ---------------- fp32 -> bf16 hi/lo split ---------------------------------
__global__ void split2(const float* __restrict__ in, __nv_bfloat16* __restrict__ hi,
                       __nv_bfloat16* __restrict__ lo, int n4)
{
    int i = blockIdx.x * blockDim.x + threadIdx.x;
    if (i >= n4) return;
    float4 v = ((const float4*)in)[i];
    uint32_t h0, l0, h1, l1;
    pack2(v.x, v.y, h0, l0);
    pack2(v.z, v.w, h1, l1);
    ((uint32_t*)hi)[i * 2] = h0;     ((uint32_t*)hi)[i * 2 + 1] = h1;
    ((uint32_t*)lo)[i * 2] = l0;     ((uint32_t*)lo)[i * 2 + 1] = l1;
}

// ---------------- GEMM: 128x64x32 tile, 2 CTAs/SM (R15/R16, frozen) --------
template<int ACT, int EPI>
__global__ void __launch_bounds__(256, 2)
gemm_pre(const __nv_bfloat16* __restrict__ Ahi, const __nv_bfloat16* __restrict__ Alo,
         const __nv_bfloat16* __restrict__ Bhi, const __nv_bfloat16* __restrict__ Blo,
         const float* __restrict__ bias, float* __restrict__ Yf,
         const float* __restrict__ Ygate,
         __nv_bfloat16* __restrict__ o1h, __nv_bfloat16* __restrict__ o1l,
         __nv_bfloat16* __restrict__ o2h, __nv_bfloat16* __restrict__ o2l,
         int K, int outCtot, int coff)
{
    extern __shared__ __align__(16) char smraw[];
    __nv_bfloat16* sA = (__nv_bfloat16*)smraw;
    __nv_bfloat16* sB = sA + 2 * 2 * 128 * ASTR;

    const int tid = threadIdx.x;
    const int lane = tid & 31, warp = tid >> 5;
    const int wm = warp >> 1, wn = warp & 1;
    const int m0 = blockIdx.x * 128;
    const int hw0 = blockIdx.y * 64;
    const int bz = blockIdx.z;
    const size_t xoff = (size_t)bz * K * HW;
    const int iters = K / 32;

    int aRow[2], aKg[2];
#pragma unroll
    for (int e = 0; e < 2; e++) {
        int i = tid + e * 256;
        aRow[e] = i >> 2;  aKg[e] = (i & 3) * 8;
    }
    const int bKr = tid >> 3, bNg = (tid & 7) * 8;

    uint4 rah[2], ral[2], rbh, rbl;
    auto loadRegs = [&](int it) {
        int k0 = it * 32;
#pragma unroll
        for (int e = 0; e < 2; e++) {
            size_t ga = (size_t)(m0 + aRow[e]) * K + k0 + aKg[e];
            rah[e] = *(const uint4*)(Ahi + ga);
            ral[e] = *(const uint4*)(Alo + ga);
        }
        size_t gb = xoff + (size_t)(k0 + bKr) * HW + hw0 + bNg;
        rbh = *(const uint4*)(Bhi + gb);
        rbl = *(const uint4*)(Blo + gb);
    };
    auto stsRegs = [&](int p) {
#pragma unroll
        for (int e = 0; e < 2; e++) {
            *(uint4*)(sA + ((p * 2 + 0) * 128 + aRow[e]) * ASTR + aKg[e]) = rah[e];
            *(uint4*)(sA + ((p * 2 + 1) * 128 + aRow[e]) * ASTR + aKg[e]) = ral[e];
        }
        *(uint4*)(sB + ((p * 2 + 0) * 32 + bKr) * BSTR + bNg) = rbh;
        *(uint4*)(sB + ((p * 2 + 1) * 32 + bKr) * BSTR + bNg) = rbl;
    };

    float acc[2][4][4];
#pragma unroll
    for (int i = 0; i < 2; i++)
#pragma unroll
        for (int j = 0; j < 4; j++)
#pragma unroll
            for (int q = 0; q < 4; q++) acc[i][j][q] = 0.f;

    const int arow = lane & 15;
    const int acol8 = (lane >> 4) << 3;
    const int bkrow = (lane & 7) + ((lane & 8) ? 8 : 0);
    const int bcol8 = (lane & 16) ? 8 : 0;

    loadRegs(0);
    stsRegs(0);
    if (iters > 1) loadRegs(1);
    __syncthreads();

    int p = 0;
    for (int it = 0; it < iters; it++) {
        if (it + 1 < iters) stsRegs(p ^ 1);
        if (it + 2 < iters) loadRegs(it + 2);

#pragma unroll
        for (int ks = 0; ks < 2; ks++) {
            unsigned ah[2][4], al[2][4], bh[4][2], bl[4][2];
            const int acol = ks * 16 + acol8;
#pragma unroll
            for (int mt = 0; mt < 2; mt++) {
                int m = wm * 32 + mt * 16 + arow;
                ldsm4(ah[mt], sA + ((p * 2 + 0) * 128 + m) * ASTR + acol);
                ldsm4(al[mt], sA + ((p * 2 + 1) * 128 + m) * ASTR + acol);
            }
            const int krow = ks * 16 + bkrow;
#pragma unroll
            for (int q = 0; q < 2; q++) {
                int j0 = wn * 32 + q * 16 + bcol8;
                unsigned r[4];
                ldsm4t(r, sB + ((p * 2 + 0) * 32 + krow) * BSTR + j0);
                bh[q * 2][0] = r[0]; bh[q * 2][1] = r[1];
                bh[q * 2 + 1][0] = r[2]; bh[q * 2 + 1][1] = r[3];
                ldsm4t(r, sB + ((p * 2 + 1) * 32 + krow) * BSTR + j0);
                bl[q * 2][0] = r[0]; bl[q * 2][1] = r[1];
                bl[q * 2 + 1][0] = r[2]; bl[q * 2 + 1][1] = r[3];
            }
#pragma unroll
            for (int mt = 0; mt < 2; mt++)
#pragma unroll
                for (int nt = 0; nt < 4; nt++) {
                    mma16816(acc[mt][nt], ah[mt], bh[nt]);
                    mma16816(acc[mt][nt], ah[mt], bl[nt]);
                    mma16816(acc[mt][nt], al[mt], bh[nt]);
                }
        }
        __syncthreads();
        p ^= 1;
    }

    const int r0 = lane >> 2, c0 = (lane & 3) * 2;
#pragma unroll
    for (int mt = 0; mt < 2; mt++) {
        int mA = m0 + wm * 32 + mt * 16 + r0;
        int mB = mA + 8;
        float bvA = bias[mA], bvB = bias[mB];
#pragma unroll
        for (int nt = 0; nt < 4; nt++) {
            int n = hw0 + wn * 32 + nt * 8 + c0;
            float v0 = acc[mt][nt][0] + bvA;
            float v1 = acc[mt][nt][1] + bvA;
            float v2 = acc[mt][nt][2] + bvB;
            float v3 = acc[mt][nt][3] + bvB;
            if (ACT) { v0 = silu(v0); v1 = silu(v1); v2 = silu(v2); v3 = silu(v3); }
            size_t oA = (size_t)bz * outCtot * HW + (size_t)(coff + mA) * HW + n;
            size_t oB = (size_t)bz * outCtot * HW + (size_t)(coff + mB) * HW + n;
            if (EPI == 0) {
                *(float2*)(Yf + oA) = make_float2(v0, v1);
                *(float2*)(Yf + oB) = make_float2(v2, v3);
            } else if (EPI == 1) {
                uint32_t h, l;
                pack2(v0, v1, h, l);
                *(uint32_t*)(o1h + oA) = h; *(uint32_t*)(o1l + oA) = l;
                *(uint32_t*)(o2h + oA) = h; *(uint32_t*)(o2l + oA) = l;
                pack2(v2, v3, h, l);
                *(uint32_t*)(o1h + oB) = h; *(uint32_t*)(o1l + oB) = l;
                *(uint32_t*)(o2h + oB) = h; *(uint32_t*)(o2l + oB) = l;
            } else {
                float2 yA = *(const float2*)(Ygate + oA);
                float2 yB = *(const float2*)(Ygate + oB);
                uint32_t h, l;
                pack2(v0 * yA.x, v1 * yA.y, h, l);
                *(uint32_t*)(o1h + oA) = h; *(uint32_t*)(o1l + oA) = l;
                pack2(v2 * yB.x, v3 * yB.y, h, l);
                *(uint32_t*)(o1h + oB) = h; *(uint32_t*)(o1l + oB) = l;
            }
        }
    }
}
#define GEMM_SMEM ((2 * 2 * 128 * ASTR + 2 * 2 * 32 * BSTR) * 2)   // 59392 B

// ---------------- fused dual-branch SPPF pooling: vectorized pairs ---------
__global__ void __launch_bounds__(512)
pool_both(const __nv_bfloat16* __restrict__ xh, const __nv_bfloat16* __restrict__ xl,
          __nv_bfloat16* __restrict__ o1h, __nv_bfloat16* __restrict__ o1l,
          __nv_bfloat16* __restrict__ o2h, __nv_bfloat16* __restrict__ o2l)
{
    extern __shared__ float sp[];
    float* si = sp;            // working plane
    float* pe = sp + 4096;     // exp plane
    float* t1 = sp + 8192;
    float* t2 = sp + 12288;
    const int ch = blockIdx.x, b = blockIdx.y;
    const int tid = threadIdx.x;
    const size_t src = ((size_t)b * 1024 + ch) * HW;

    for (int i = tid; i < 4096; i += 512)
        si[i] = __bfloat162float(xh[src + i]) + __bfloat162float(xl[src + i]);
    __syncthreads();

    // ---- branch 1: TMaxAvg ----
    for (int s = 0; s < 3; s++) {
        for (int j = tid; j < 2048; j += 512) {
            int i0 = j << 1;
            int c = i0 & 63;                 // even
            const float* row = &si[i0 - c];
            bool vA = (c >= 2), vC = (c <= 60);
            float2 A = vA ? *(const float2*)&row[c - 2] : make_float2(0.f, 0.f);
            float2 B = *(const float2*)&row[c];
            float2 C = vC ? *(const float2*)&row[c + 2] : make_float2(0.f, 0.f);
            float mx0 = fmaxf(B.x, B.y), sm0 = B.x + B.y;
            float mx1 = mx0,              sm1 = sm0;
            if (vA) { mx0 = fmaxf(mx0, fmaxf(A.x, A.y)); sm0 += A.x + A.y;
                      mx1 = fmaxf(mx1, A.y);             sm1 += A.y; }
            if (vC) { mx0 = fmaxf(mx0, C.x);             sm0 += C.x;
                      mx1 = fmaxf(mx1, fmaxf(C.x, C.y)); sm1 += C.x + C.y; }
            *(float2*)&t1[i0] = make_float2(mx0, mx1);
            *(float2*)&t2[i0] = make_float2(sm0, sm1);
        }
        __syncthreads();
        size_t dst = ((size_t)b * 1024 + (s + 1) * 256 + ch) * HW;
        for (int j = tid; j < 2048; j += 512) {
            int i0 = j << 1;
            int c = i0 & 63, r = i0 >> 6;
            float2 m = make_float2(-INFINITY, -INFINITY), sm = make_float2(0.f, 0.f);
#pragma unroll
            for (int d = -2; d <= 2; d++) {
                int rr = r + d;
                if (rr >= 0 && rr < 64) {
                    float2 v1 = *(const float2*)&t1[rr * 64 + c];
                    float2 v2 = *(const float2*)&t2[rr * 64 + c];
                    m.x = fmaxf(m.x, v1.x); m.y = fmaxf(m.y, v1.y);
                    sm.x += v2.x; sm.y += v2.y;
                }
            }
            float v0 = 0.9f * m.x + 0.004f * sm.x;
            float v1 = 0.9f * m.y + 0.004f * sm.y;
            *(float2*)&si[i0] = make_float2(v0, v1);
            uint32_t h, l;
            pack2(v0, v1, h, l);
            *(uint32_t*)(o1h + dst + i0) = h;
            *(uint32_t*)(o1l + dst + i0) = l;
        }
        __syncthreads();
    }

    // reload pristine input for branch 2 (L2-warm)
    for (int i = tid; i < 4096; i += 512)
        si[i] = __bfloat162float(xh[src + i]) + __bfloat162float(xl[src + i]);
    __syncthreads();

    // ---- branch 2: RWPool ----
    for (int s = 0; s < 3; s++) {
        for (int j = tid; j < 2048; j += 512) {
            int i0 = j << 1;
            float2 v = *(const float2*)&si[i0];
            *(float2*)&pe[i0] = make_float2(__expf(v.x), __expf(v.y));
        }
        __syncthreads();
        for (int j = tid; j < 2048; j += 512) {
            int i0 = j << 1;
            int c = i0 & 63;
            const float* vrow = &si[i0 - c];
            const float* erow = &pe[i0 - c];
            bool vA = (c >= 2), vC = (c <= 60);
            float2 Av = vA ? *(const float2*)&vrow[c - 2] : make_float2(0.f, 0.f);
            float2 Bv = *(const float2*)&vrow[c];
            float2 Cv = vC ? *(const float2*)&vrow[c + 2] : make_float2(0.f, 0.f);
            float2 Ae = vA ? *(const float2*)&erow[c - 2] : make_float2(0.f, 0.f);
            float2 Be = *(const float2*)&erow[c];
            float2 Ce = vC ? *(const float2*)&erow[c + 2] : make_float2(0.f, 0.f);
            float se0 = Be.x + Be.y, sx0 = Be.x * Bv.x + Be.y * Bv.y;
            float se1 = se0,         sx1 = sx0;
            if (vA) { se0 += Ae.x + Ae.y; sx0 += Ae.x * Av.x + Ae.y * Av.y;
                      se1 += Ae.y;        sx1 += Ae.y * Av.y; }
            if (vC) { se0 += Ce.x;        sx0 += Ce.x * Cv.x;
                      se1 += Ce.x + Ce.y; sx1 += Ce.x * Cv.x + Ce.y * Cv.y; }
            *(float2*)&t1[i0] = make_float2(se0, se1);
            *(float2*)&t2[i0] = make_float2(sx0, sx1);
        }
        __syncthreads();
        size_t dst = ((size_t)b * 1024 + (s + 1) * 256 + ch) * HW;
        for (int j = tid; j < 2048; j += 512) {
            int i0 = j << 1;
            int c = i0 & 63, r = i0 >> 6;
            float2 den = make_float2(0.f, 0.f), num = make_float2(0.f, 0.f);
#pragma unroll
            for (int d = -2; d <= 2; d++) {
                int rr = r + d;
                if (rr >= 0 && rr < 64) {
                    float2 v1 = *(const float2*)&t1[rr * 64 + c];
                    float2 v2 = *(const float2*)&t2[rr * 64 + c];
                    den.x += v1.x; den.y += v1.y;
                    num.x += v2.x; num.y += v2.y;
                }
            }
            float v0 = num.x / (den.x + 1e-6f);
            float v1 = num.y / (den.y + 1e-6f);
            *(float2*)&si[i0] = make_float2(v0, v1);
            uint32_t h, l;
            pack2(v0, v1, h, l);
            *(uint32_t*)(o2h + dst + i0) = h;
            *(uint32_t*)(o2l + dst + i0) = l;
        }
        __syncthreads();
    }
}
#define POOL_SMEM (4 * 4096 * 4)   // 65536 B -> 3 CTAs/SM

// ---------------- fused LSKA depthwise chain: vectorized pairs -------------
__global__ void __launch_bounds__(512)
dw_fused(const float* __restrict__ y,
         const float* __restrict__ w1, const float* __restrict__ b1,
         const float* __restrict__ w2, const float* __restrict__ b2,
         const float* __restrict__ w3, const float* __restrict__ b3,
         const float* __restrict__ w4, const float* __restrict__ b4,
         __nv_bfloat16* __restrict__ oh, __nv_bfloat16* __restrict__ ol)
{
    __shared__ float s0[4096], s1[4096];
    const int ch = blockIdx.x, b = blockIdx.y;
    const int tid = threadIdx.x;
    const size_t off = ((size_t)b * 1024 + ch) * HW;

    for (int i = tid; i < 4096; i += 512) s0[i] = y[off + i];
    __syncthreads();

    {   // pass 1: horizontal dil 1
        float wa = w1[ch * 3], wb = w1[ch * 3 + 1], wc = w1[ch * 3 + 2], bb = b1[ch];
        for (int j = tid; j < 2048; j += 512) {
            int i0 = j << 1, c = i0 & 63;
            const float* row = &s0[i0 - c];
            float2 B = *(const float2*)&row[c];
            float prev = (c >= 1) ? row[c - 1] : 0.f;
            float nxt  = (c <= 61) ? row[c + 2] : 0.f;
            float a0 = bb + wb * B.x + wc * B.y;
            if (c >= 1) a0 = fmaf(wa, prev, a0);
            float a1 = bb + wa * B.x + wb * B.y;
            if (c <= 61) a1 = fmaf(wc, nxt, a1);
            *(float2*)&s1[i0] = make_float2(a0, a1);
        }
    }
    __syncthreads();
    {   // pass 2: vertical dil 1
        float wa = w2[ch * 3], wb = w2[ch * 3 + 1], wc = w2[ch * 3 + 2], bb = b2[ch];
        for (int j = tid; j < 2048; j += 512) {
            int i0 = j << 1, r = i0 >> 6;
            float2 B = *(const float2*)&s1[i0];
            float2 a = make_float2(bb + wb * B.x, bb + wb * B.y);
            if (r >= 1) {
                float2 U = *(const float2*)&s1[i0 - 64];
                a.x = fmaf(wa, U.x, a.x); a.y = fmaf(wa, U.y, a.y);
            }
            if (r <= 62) {
                float2 D = *(const float2*)&s1[i0 + 64];
                a.x = fmaf(wc, D.x, a.x); a.y = fmaf(wc, D.y, a.y);
            }
            *(float2*)&s0[i0] = a;
        }
    }
    __syncthreads();
    {   // pass 3: horizontal dil 2
        float wa = w3[ch * 3], wb = w3[ch * 3 + 1], wc = w3[ch * 3 + 2], bb = b3[ch];
        for (int j = tid; j < 2048; j += 512) {
            int i0 = j << 1, c = i0 & 63;
            const float* row = &s0[i0 - c];
            bool vA = (c >= 2), vC = (c <= 60);
            float2 A = vA ? *(const float2*)&row[c - 2] : make_float2(0.f, 0.f);
            float2 B = *(const float2*)&row[c];
            float2 C = vC ? *(const float2*)&row[c + 2] : make_float2(0.f, 0.f);
            float a0 = bb + wb * B.x;
            float a1 = bb + wb * B.y;
            if (vA) { a0 = fmaf(wa, A.x, a0); a1 = fmaf(wa, A.y, a1); }
            if (vC) { a0 = fmaf(wc, C.x, a0); a1 = fmaf(wc, C.y, a1); }
            *(float2*)&s1[i0] = make_float2(a0, a1);
        }
    }
    __syncthreads();
    {   // pass 4: vertical dil 2 -> split gmem
        float wa = w4[ch * 3], wb = w4[ch * 3 + 1], wc = w4[ch * 3 + 2], bb = b4[ch];
        for (int j = tid; j < 2048; j += 512) {
            int i0 = j << 1, r = i0 >> 6;
            float2 B = *(const float2*)&s1[i0];
            float2 a = make_float2(bb + wb * B.x, bb + wb * B.y);
            if (r >= 2) {
                float2 U = *(const float2*)&s1[i0 - 128];
                a.x = fmaf(wa, U.x, a.x); a.y = fmaf(wa, U.y, a.y);
            }
            if (r <= 61) {
                float2 D = *(const float2*)&s1[i0 + 128];
                a.x = fmaf(wc, D.x, a.x); a.y = fmaf(wc, D.y, a.y);
            }
            uint32_t h, l;
            pack2(a.x, a.y, h, l);
            *(uint32_t*)(oh + off + i0) = h;
            *(uint32_t*)(ol + off + i0) = l;
        }
    }
}

// ---------------- launch ----------------------------------------------------
extern "C" void kernel_launch(void* const* d_in, const int* in_sizes, int n_in,
                              void* d_out, int out_size)
{
    const float* x       = (const float*)d_in[0];
    const float* w_sta   = (const float*)d_in[1];
    const float* b_sta   = (const float*)d_in[2];
    const float* w_cv1   = (const float*)d_in[3];
    const float* b_cv1   = (const float*)d_in[4];
    const float* w_cv2   = (const float*)d_in[5];
    const float* b_cv2   = (const float*)d_in[6];
    const float* w_cvend = (const float*)d_in[7];
    const float* b_cvend = (const float*)d_in[8];
    const float* w_dwh   = (const float*)d_in[9];
    const float* b_dwh   = (const float*)d_in[10];
    const float* w_dwv   = (const float*)d_in[11];
    const float* b_dwv   = (const float*)d_in[12];
    const float* w_ddwh  = (const float*)d_in[13];
    const float* b_ddwh  = (const float*)d_in[14];
    const float* w_ddwv  = (const float*)d_in[15];
    const float* b_ddwv  = (const float*)d_in[16];
    const float* w_c1    = (const float*)d_in[17];
    const float* b_c1    = (const float*)d_in[18];

    float *y;
    __nv_bfloat16 *x0h, *x0l, *xh1, *xl1, *xh2, *xl2, *bh, *bl, *gh, *gl;
    __nv_bfloat16 *wsh, *wsl, *w1h, *w1l, *w2h, *w2l, *weh, *wel, *wch, *wcl;
    cudaGetSymbolAddress((void**)&y,   g_y);
    cudaGetSymbolAddress((void**)&x0h, g_x0h); cudaGetSymbolAddress((void**)&x0l, g_x0l);
    cudaGetSymbolAddress((void**)&xh1, g_xh1); cudaGetSymbolAddress((void**)&xl1, g_xl1);
    cudaGetSymbolAddress((void**)&xh2, g_xh2); cudaGetSymbolAddress((void**)&xl2, g_xl2);
    cudaGetSymbolAddress((void**)&bh,  g_bh);  cudaGetSymbolAddress((void**)&bl,  g_bl);
    cudaGetSymbolAddress((void**)&gh,  g_gh);  cudaGetSymbolAddress((void**)&gl,  g_gl);
    cudaGetSymbolAddress((void**)&wsh, g_wsh); cudaGetSymbolAddress((void**)&wsl, g_wsl);
    cudaGetSymbolAddress((void**)&w1h, g_w1h); cudaGetSymbolAddress((void**)&w1l, g_w1l);
    cudaGetSymbolAddress((void**)&w2h, g_w2h); cudaGetSymbolAddress((void**)&w2l, g_w2l);
    cudaGetSymbolAddress((void**)&weh, g_weh); cudaGetSymbolAddress((void**)&wel, g_wel);
    cudaGetSymbolAddress((void**)&wch, g_wch); cudaGetSymbolAddress((void**)&wcl, g_wcl);

    cudaFuncSetAttribute(gemm_pre<1, 1>, cudaFuncAttributeMaxDynamicSharedMemorySize, GEMM_SMEM);
    cudaFuncSetAttribute(gemm_pre<1, 0>, cudaFuncAttributeMaxDynamicSharedMemorySize, GEMM_SMEM);
    cudaFuncSetAttribute(gemm_pre<0, 2>, cudaFuncAttributeMaxDynamicSharedMemorySize, GEMM_SMEM);
    cudaFuncSetAttribute(pool_both, cudaFuncAttributeMaxDynamicSharedMemorySize, POOL_SMEM);
    auto g4 = [](int n) { return (n / 4 + 255) / 256; };

    // 1) split input, 2) split sta weight
    split2<<<g4(NB * 512 * HW), 256>>>(x, x0h, x0l, NB * 512 * HW / 4);
    split2<<<g4(256 * 512), 256>>>(w_sta, wsh, wsl, 256 * 512 / 4);
    // 3) sta: 512->256 + SiLU, split-dup into (xh1,xl1)/(xh2,xl2) ch 0..255
    gemm_pre<1, 1><<<dim3(2, 64, NB), 256, GEMM_SMEM>>>(
        wsh, wsl, x0h, x0l, b_sta, nullptr, nullptr, xh1, xl1, xh2, xl2, 512, 1024, 0);
    // 4) fused dual-branch pooling (ch 256..1023)
    pool_both<<<dim3(256, NB), 512, POOL_SMEM>>>(xh1, xl1, xh1, xl1, xh2, xl2);
    // 5) split cv1 weight, 6) cv1 -> y[0:512]
    split2<<<g4(512 * 1024), 256>>>(w_cv1, w1h, w1l, 512 * 1024 / 4);
    gemm_pre<1, 0><<<dim3(4, 64, NB), 256, GEMM_SMEM>>>(
        w1h, w1l, xh1, xl1, b_cv1, y, nullptr, nullptr, nullptr, nullptr, nullptr, 1024, 1024, 0);
    // 7) split cv2 weight, 8) cv2 -> y[512:1024]
    split2<<<g4(512 * 1024), 256>>>(w_cv2, w2h, w2l, 512 * 1024 / 4);
    gemm_pre<1, 0><<<dim3(4, 64, NB), 256, GEMM_SMEM>>>(
        w2h, w2l, xh2, xl2, b_cv2, y, nullptr, nullptr, nullptr, nullptr, nullptr, 1024, 1024, 512);
    // 9) fused LSKA depthwise chain: y -> split (bh,bl)
    dw_fused<<<dim3(1024, NB), 512>>>(y, w_dwh, b_dwh, w_dwv, b_dwv,
                                      w_ddwh, b_ddwh, w_ddwv, b_ddwv, bh, bl);
    // 10) split c1 weight, 11) c1 (gate fused) -> (gh,gl)
    split2<<<g4(1024 * 1024), 256>>>(w_c1, wch, wcl, 1024 * 1024 / 4);
    gemm_pre<0, 2><<<dim3(8, 64, NB), 256, GEMM_SMEM>>>(
        wch, wcl, bh, bl, b_c1, nullptr, y, gh, gl, nullptr, nullptr, 1024, 1024, 0);
    // 12) split cvend weight, 13) cvend -> output
    split2<<<g4(512 * 1024), 256>>>(w_cvend, weh, wel, 512 * 1024 / 4);
    gemm_pre<1, 0><<<dim3(4, 64, NB), 256, GEMM_SMEM>>>(
        weh, wel, gh, gl, b_cvend, (float*)d_out, nullptr, nullptr, nullptr, nullptr, nullptr,
        1024, 512, 0);
}